// round 10
// baseline (speedup 1.0000x reference)
#include <cuda_runtime.h>
#include <cuda_bf16.h>
#include <math.h>
#include <stdint.h>

#define EMBED 2048
#define HEADS 16
#define HD    128
#define DFF   8192
#define BATCH 2
#define SEQ   2048
#define TOKENS (BATCH*SEQ)
#define LN_EPS 1e-5f

typedef __nv_bfloat16 bf16;

// ---------------- scratch ----------------
__device__ __align__(1024) bf16 g_xhi[(size_t)TOKENS*EMBED], g_xlo[(size_t)TOKENS*EMBED];
__device__ __align__(1024) bf16 g_qhi[(size_t)TOKENS*EMBED], g_qlo[(size_t)TOKENS*EMBED];
__device__ __align__(1024) bf16 g_khi[(size_t)TOKENS*EMBED], g_klo[(size_t)TOKENS*EMBED];
__device__ __align__(1024) bf16 g_vthi[(size_t)TOKENS*EMBED], g_vtlo[(size_t)TOKENS*EMBED];
__device__ __align__(1024) float g_s [(size_t)BATCH*HEADS*SEQ*SEQ];
__device__ __align__(1024) bf16 g_shi[(size_t)BATCH*HEADS*SEQ*SEQ], g_slo[(size_t)BATCH*HEADS*SEQ*SEQ];
__device__ __align__(1024) bf16 g_aohi[(size_t)TOKENS*EMBED], g_aolo[(size_t)TOKENS*EMBED];
__device__ __align__(1024) float g_t1[(size_t)TOKENS*EMBED];
__device__ __align__(1024) float g_h [(size_t)TOKENS*EMBED];
__device__ __align__(1024) bf16 g_hhi[(size_t)TOKENS*EMBED], g_hlo[(size_t)TOKENS*EMBED];
__device__ __align__(1024) bf16 g_f1hi[(size_t)TOKENS*DFF],  g_f1lo[(size_t)TOKENS*DFF];
__device__ __align__(1024) bf16 g_wqh[(size_t)EMBED*EMBED], g_wql[(size_t)EMBED*EMBED];
__device__ __align__(1024) bf16 g_wkh[(size_t)EMBED*EMBED], g_wkl[(size_t)EMBED*EMBED];
__device__ __align__(1024) bf16 g_wvh[(size_t)EMBED*EMBED], g_wvl[(size_t)EMBED*EMBED];
__device__ __align__(1024) bf16 g_woh[(size_t)EMBED*EMBED], g_wol[(size_t)EMBED*EMBED];
__device__ __align__(1024) bf16 g_w1h[(size_t)EMBED*DFF],   g_w1l[(size_t)EMBED*DFF];
__device__ __align__(1024) bf16 g_w2h[(size_t)EMBED*DFF],   g_w2l[(size_t)EMBED*DFF];

// ---------------- helpers ----------------
__device__ __forceinline__ uint32_t smem_u32(const void* p) {
    return (uint32_t)__cvta_generic_to_shared(p);
}
__device__ __forceinline__ void cp16(uint32_t dst, const void* src) {
    asm volatile("cp.async.cg.shared.global [%0], [%1], 16;\n" :: "r"(dst), "l"(src));
}
__device__ __forceinline__ void cp_commit() { asm volatile("cp.async.commit_group;\n"); }
template<int Ngrp> __device__ __forceinline__ void cp_wait() {
    asm volatile("cp.async.wait_group %0;\n" :: "n"(Ngrp));
}
__device__ __forceinline__ void ldsm4(uint32_t* r, uint32_t addr) {
    asm volatile("ldmatrix.sync.aligned.m8n8.x4.shared.b16 {%0,%1,%2,%3}, [%4];"
                 : "=r"(r[0]), "=r"(r[1]), "=r"(r[2]), "=r"(r[3]) : "r"(addr));
}
__device__ __forceinline__ void mma16816(float* c, const uint32_t* a, const uint32_t* b) {
    asm volatile(
        "mma.sync.aligned.m16n8k16.row.col.f32.bf16.bf16.f32 "
        "{%0,%1,%2,%3}, {%4,%5,%6,%7}, {%8,%9}, {%0,%1,%2,%3};\n"
        : "+f"(c[0]), "+f"(c[1]), "+f"(c[2]), "+f"(c[3])
        : "r"(a[0]), "r"(a[1]), "r"(a[2]), "r"(a[3]), "r"(b[0]), "r"(b[1]));
}
__device__ __forceinline__ uint32_t swz(uint32_t off) { return off ^ ((off >> 3) & 0x70); }

__device__ __forceinline__ void split_write(bf16* hi, bf16* lo, size_t o, float v) {
    bf16 h = __float2bfloat16(v);
    hi[o] = h;
    lo[o] = __float2bfloat16(v - __bfloat162float(h));
}

// ---------------- fused weight prep ----------------
__global__ __launch_bounds__(256)
void prep_weights(const float* __restrict__ Wq, const float* __restrict__ Wk,
                  const float* __restrict__ Wv, const float* __restrict__ Wo,
                  const float* __restrict__ W1, const float* __restrict__ W2)
{
    __shared__ float t[32][33];
    const int bidx = blockIdx.x;

    const float* in; bf16* hi; bf16* lo; int R, C, tbase;
    if (bidx < 16384) {
        R = EMBED; C = EMBED;
        if (bidx < 4096)       { in = Wq; hi = g_wqh; lo = g_wql; tbase = 0; }
        else if (bidx < 8192)  { in = Wk; hi = g_wkh; lo = g_wkl; tbase = 4096; }
        else if (bidx < 12288) { in = Wv; hi = g_wvh; lo = g_wvl; tbase = 8192; }
        else                   { in = Wo; hi = g_woh; lo = g_wol; tbase = 12288; }
    } else if (bidx < 32768) {
        in = W1; hi = g_w1h; lo = g_w1l; R = EMBED; C = DFF; tbase = 16384;
    } else {
        in = W2; hi = g_w2h; lo = g_w2l; R = DFF; C = EMBED; tbase = 32768;
    }
    const int t0 = bidx - tbase;
    const int tiles_x = C >> 5;
    const int c0 = (t0 % tiles_x) << 5;
    const int r0 = (t0 / tiles_x) << 5;

    const int tx = threadIdx.x & 31, ty = threadIdx.x >> 5;
    #pragma unroll
    for (int i = 0; i < 32; i += 8)
        t[ty + i][tx] = in[(size_t)(r0 + ty + i) * C + c0 + tx];
    __syncthreads();
    #pragma unroll
    for (int i = 0; i < 32; i += 8)
        split_write(hi, lo, (size_t)(c0 + ty + i) * R + r0 + tx, t[tx][ty + i]);
}

// ---------------- elementwise fp32 -> hi/lo ----------------
__global__ __launch_bounds__(256)
void split_kernel(const float* __restrict__ in, bf16* __restrict__ hi, bf16* __restrict__ lo, size_t n)
{
    size_t i = (size_t)blockIdx.x * 1024 + threadIdx.x;
    #pragma unroll
    for (int j = 0; j < 4; j++) {
        size_t o = i + (size_t)j * 256;
        if (o < n) split_write(hi, lo, o, in[o]);
    }
}

// ---------------- bf16x3 mma.sync GEMM ----------------
// CTA tile 256x128, 16 warps (512 thr) of 64x32, K-chunk 64, double buffered.
enum { EP_PLAIN=0, EP_QK=1, EP_VT=2, EP_MERGE=3, EP_RES=4, EP_GELU=5 };

#define ST_AH 0
#define ST_AL 32768
#define ST_BH 65536
#define ST_BL 81920
#define STAGE 98304
#define SMEM_DYN (2*STAGE + 1024)

template<int MODE>
__global__ __launch_bounds__(512)
void tc_gemm(const bf16* __restrict__ Ahi, const bf16* __restrict__ Alo,
             const bf16* __restrict__ Bhi, const bf16* __restrict__ Blo,
             const float* __restrict__ bias, const float* __restrict__ res,
             void* __restrict__ O0, void* __restrict__ O1,
             int M, int N, int K, float scale, long sA, long sB)
{
    extern __shared__ char dsm[];
    const uint32_t tile0 = (smem_u32(dsm) + 1023u) & ~1023u;

    const int tid = threadIdx.x, warp = tid >> 5, lane = tid & 31;
    const int wm = warp >> 2;       // 0..3 -> m offset 64
    const int wn = warp & 3;        // 0..3 -> n offset 32
    const int bz = blockIdx.z;
    const int bm = blockIdx.y * 256, bn = blockIdx.x * 128;

    const bf16* Ah_g = Ahi + (size_t)bz * sA;
    const bf16* Al_g = Alo + (size_t)bz * sA;
    const bf16* Bh_g = Bhi + (size_t)bz * sB;
    const bf16* Bl_g = Blo + (size_t)bz * sB;

    float acc[4][4][4];
    #pragma unroll
    for (int i = 0; i < 4; i++)
        #pragma unroll
        for (int j = 0; j < 4; j++)
            #pragma unroll
            for (int p = 0; p < 4; p++) acc[i][j][p] = 0.f;

    const int NIT = K >> 6;

    auto load_chunk = [&](int stage, int k0) {
        const uint32_t st = tile0 + (uint32_t)stage * STAGE;
        #pragma unroll
        for (int i = 0; i < 4; i++) {              // A: 256 rows x 8 chunks / 512 thr
            const int idx = i * 512 + tid;
            const int r = idx >> 3, c = idx & 7;
            const uint32_t so = swz((uint32_t)(r * 128 + c * 16));
            cp16(st + ST_AH + so, Ah_g + (size_t)(bm + r) * K + k0 + c * 8);
            cp16(st + ST_AL + so, Al_g + (size_t)(bm + r) * K + k0 + c * 8);
        }
        #pragma unroll
        for (int i = 0; i < 2; i++) {              // B: 128 rows x 8 chunks / 512 thr
            const int idx = i * 512 + tid;
            const int r = idx >> 3, c = idx & 7;
            const uint32_t so = swz((uint32_t)(r * 128 + c * 16));
            cp16(st + ST_BH + so, Bh_g + (size_t)(bn + r) * K + k0 + c * 8);
            cp16(st + ST_BL + so, Bl_g + (size_t)(bn + r) * K + k0 + c * 8);
        }
        cp_commit();
    };

    load_chunk(0, 0);
    if (NIT > 1) load_chunk(1, 64);

    const uint32_t lrow = lane & 15;
    const uint32_t lkb  = (lane >> 4) * 16;   // byte offset for k+8 group

    for (int it = 0; it < NIT; it++) {
        const int cur = it & 1;
        if (it + 1 < NIT) cp_wait<1>(); else cp_wait<0>();
        __syncthreads();

        const uint32_t st = tile0 + (uint32_t)cur * STAGE;

        #pragma unroll
        for (int ks = 0; ks < 4; ks++) {
            const uint32_t kb = (uint32_t)ks * 32 + lkb;

            uint32_t ah[4][4];
            #pragma unroll
            for (int mt = 0; mt < 4; mt++)
                ldsm4(ah[mt], st + ST_AH + swz((uint32_t)((wm*64 + mt*16 + lrow) * 128) + kb));

            uint32_t bh[2][4], bl[2][4];
            #pragma unroll
            for (int g = 0; g < 2; g++) {
                const uint32_t so = swz((uint32_t)((wn*32 + g*16 + lrow) * 128) + kb);
                ldsm4(bh[g], st + ST_BH + so);
                ldsm4(bl[g], st + ST_BL + so);
            }

            // pass 1: hh
            #pragma unroll
            for (int mt = 0; mt < 4; mt++)
                #pragma unroll
                for (int nt = 0; nt < 4; nt++) {
                    const int g = nt >> 1, s2 = nt & 1;
                    uint32_t bf2r[2] = { bh[g][s2], bh[g][s2 + 2] };
                    mma16816(acc[mt][nt], ah[mt], bf2r);
                }
            // pass 2: hl
            #pragma unroll
            for (int mt = 0; mt < 4; mt++)
                #pragma unroll
                for (int nt = 0; nt < 4; nt++) {
                    const int g = nt >> 1, s2 = nt & 1;
                    uint32_t bf2r[2] = { bl[g][s2], bl[g][s2 + 2] };
                    mma16816(acc[mt][nt], ah[mt], bf2r);
                }
            // pass 3: lh (al reuses bl's dead registers)
            uint32_t al[4][4];
            #pragma unroll
            for (int mt = 0; mt < 4; mt++)
                ldsm4(al[mt], st + ST_AL + swz((uint32_t)((wm*64 + mt*16 + lrow) * 128) + kb));
            #pragma unroll
            for (int mt = 0; mt < 4; mt++)
                #pragma unroll
                for (int nt = 0; nt < 4; nt++) {
                    const int g = nt >> 1, s2 = nt & 1;
                    uint32_t bf2r[2] = { bh[g][s2], bh[g][s2 + 2] };
                    mma16816(acc[mt][nt], al[mt], bf2r);
                }
        }
        __syncthreads();
        if (it + 2 < NIT) load_chunk(cur, (it + 2) * 64);
    }

    // ---- epilogue ----
    #pragma unroll
    for (int mt = 0; mt < 4; mt++) {
        const int m0 = bm + wm * 64 + mt * 16 + (lane >> 2);
        #pragma unroll
        for (int nt = 0; nt < 4; nt++) {
            const int n0 = bn + wn * 32 + nt * 8 + (lane & 3) * 2;
            #pragma unroll
            for (int i = 0; i < 4; i++) {
                const int m = m0 + ((i >= 2) ? 8 : 0);
                const int n = n0 + (i & 1);
                float v = acc[mt][nt][i] * scale;

                if (MODE == EP_PLAIN) {
                    ((float*)O0)[(size_t)bz * ((size_t)M * N) + (size_t)m * N + n] = v;
                } else if (MODE == EP_QK) {
                    v += bias[n];
                    const int b = m >> 11, nn = m & (SEQ - 1);
                    const int h = n >> 7,  d = n & (HD - 1);
                    split_write((bf16*)O0, (bf16*)O1,
                                (((size_t)(b * HEADS + h)) * SEQ + nn) * HD + d, v);
                } else if (MODE == EP_VT) {
                    v += bias[n];
                    const int b = m >> 11, nn = m & (SEQ - 1);
                    const int h = n >> 7,  d = n & (HD - 1);
                    split_write((bf16*)O0, (bf16*)O1,
                                (((size_t)(b * HEADS + h)) * HD + d) * SEQ + nn, v);
                } else if (MODE == EP_MERGE) {
                    const int b = bz >> 4, h = bz & 15;
                    split_write((bf16*)O0, (bf16*)O1,
                                ((size_t)(b * SEQ + m)) * EMBED + h * HD + n, v);
                } else if (MODE == EP_RES) {
                    v += bias[n] + res[(size_t)m * N + n];
                    ((float*)O0)[(size_t)m * N + n] = v;
                } else { // EP_GELU
                    v += bias[n];
                    v = 0.5f * v * (1.f + erff(v * 0.70710678118654752f));
                    split_write((bf16*)O0, (bf16*)O1, (size_t)m * N + n, v);
                }
            }
        }
    }
}

// ---------------- softmax: fp32 in -> hi/lo bf16 out ----------------
__global__ __launch_bounds__(256)
void softmax_kernel(const float* __restrict__ S, bf16* __restrict__ Phi, bf16* __restrict__ Plo)
{
    __shared__ float red[256];
    const size_t row = blockIdx.x;
    const float* p = S + row * (size_t)SEQ;
    const int tid = threadIdx.x;

    float v[8];
    float lmax = -1e30f;
    #pragma unroll
    for (int i = 0; i < 8; i++) { v[i] = p[tid + i*256]; lmax = fmaxf(lmax, v[i]); }
    red[tid] = lmax; __syncthreads();
    for (int s = 128; s > 0; s >>= 1) { if (tid < s) red[tid] = fmaxf(red[tid], red[tid+s]); __syncthreads(); }
    const float m = red[0]; __syncthreads();

    float lsum = 0.f;
    #pragma unroll
    for (int i = 0; i < 8; i++) { v[i] = expf(v[i] - m); lsum += v[i]; }
    red[tid] = lsum; __syncthreads();
    for (int s = 128; s > 0; s >>= 1) { if (tid < s) red[tid] += red[tid+s]; __syncthreads(); }
    const float inv = 1.f / red[0];

    #pragma unroll
    for (int i = 0; i < 8; i++)
        split_write(Phi, Plo, row * (size_t)SEQ + tid + i*256, v[i] * inv);
}

// ---------------- LayerNorm ----------------
template<int BF>
__global__ __launch_bounds__(256)
void ln_kernel(const float* __restrict__ in, const float* __restrict__ g,
               const float* __restrict__ b, float* __restrict__ outf,
               bf16* __restrict__ ohi, bf16* __restrict__ olo)
{
    __shared__ float r1[256], r2[256];
    const size_t row = blockIdx.x;
    const float* p = in + row * (size_t)EMBED;
    const int tid = threadIdx.x;

    float v[8];
    float s = 0.f, ss = 0.f;
    #pragma unroll
    for (int i = 0; i < 8; i++) { v[i] = p[tid + i*256]; s += v[i]; ss += v[i]*v[i]; }
    r1[tid] = s; r2[tid] = ss; __syncthreads();
    for (int st = 128; st > 0; st >>= 1) {
        if (tid < st) { r1[tid] += r1[tid+st]; r2[tid] += r2[tid+st]; }
        __syncthreads();
    }
    const float mu  = r1[0] * (1.f / EMBED);
    const float var = r2[0] * (1.f / EMBED) - mu * mu;
    const float rs  = rsqrtf(var + LN_EPS);

    #pragma unroll
    for (int i = 0; i < 8; i++) {
        const int c = tid + i*256;
        const float o = (v[i] - mu) * rs * g[c] + b[c];
        outf[row * (size_t)EMBED + c] = o;
        if (BF) split_write(ohi, olo, row * (size_t)EMBED + c, o);
    }
}

// ---------------- launch ----------------
extern "C" void kernel_launch(void* const* d_in, const int* in_sizes, int n_in,
                              void* d_out, int out_size)
{
    const float* x   = (const float*)d_in[0];
    const float* Wq  = (const float*)d_in[1];
    const float* bq  = (const float*)d_in[2];
    const float* Wk  = (const float*)d_in[3];
    const float* bk  = (const float*)d_in[4];
    const float* Wv  = (const float*)d_in[5];
    const float* bv  = (const float*)d_in[6];
    const float* Wo  = (const float*)d_in[7];
    const float* bo  = (const float*)d_in[8];
    const float* g1  = (const float*)d_in[9];
    const float* b1  = (const float*)d_in[10];
    const float* g2  = (const float*)d_in[11];
    const float* b2  = (const float*)d_in[12];
    const float* W1  = (const float*)d_in[13];
    const float* bf1 = (const float*)d_in[14];
    const float* W2  = (const float*)d_in[15];
    const float* bf2 = (const float*)d_in[16];
    float* out = (float*)d_out;

    bf16 *xhi,*xlo,*qhi,*qlo,*khi,*klo,*vthi,*vtlo,*shi,*slo,*aohi,*aolo,*hhi,*hlo,*f1hi,*f1lo;
    bf16 *wqh,*wql,*wkh,*wkl,*wvh,*wvl,*woh,*wol,*w1h,*w1l,*w2h,*w2l;
    float *s, *t1, *h;
    cudaGetSymbolAddress((void**)&xhi, g_xhi); cudaGetSymbolAddress((void**)&xlo, g_xlo);
    cudaGetSymbolAddress((void**)&qhi, g_qhi); cudaGetSymbolAddress((void**)&qlo, g_qlo);
    cudaGetSymbolAddress((void**)&khi, g_khi); cudaGetSymbolAddress((void**)&klo, g_klo);
    cudaGetSymbolAddress((void**)&vthi,g_vthi);cudaGetSymbolAddress((void**)&vtlo,g_vtlo);
    cudaGetSymbolAddress((void**)&s,   g_s);
    cudaGetSymbolAddress((void**)&shi, g_shi); cudaGetSymbolAddress((void**)&slo, g_slo);
    cudaGetSymbolAddress((void**)&aohi,g_aohi);cudaGetSymbolAddress((void**)&aolo,g_aolo);
    cudaGetSymbolAddress((void**)&t1,  g_t1);  cudaGetSymbolAddress((void**)&h,   g_h);
    cudaGetSymbolAddress((void**)&hhi, g_hhi); cudaGetSymbolAddress((void**)&hlo, g_hlo);
    cudaGetSymbolAddress((void**)&f1hi,g_f1hi);cudaGetSymbolAddress((void**)&f1lo,g_f1lo);
    cudaGetSymbolAddress((void**)&wqh, g_wqh); cudaGetSymbolAddress((void**)&wql, g_wql);
    cudaGetSymbolAddress((void**)&wkh, g_wkh); cudaGetSymbolAddress((void**)&wkl, g_wkl);
    cudaGetSymbolAddress((void**)&wvh, g_wvh); cudaGetSymbolAddress((void**)&wvl, g_wvl);
    cudaGetSymbolAddress((void**)&woh, g_woh); cudaGetSymbolAddress((void**)&wol, g_wol);
    cudaGetSymbolAddress((void**)&w1h, g_w1h); cudaGetSymbolAddress((void**)&w1l, g_w1l);
    cudaGetSymbolAddress((void**)&w2h, g_w2h); cudaGetSymbolAddress((void**)&w2l, g_w2l);

    cudaFuncSetAttribute(tc_gemm<EP_PLAIN>, cudaFuncAttributeMaxDynamicSharedMemorySize, SMEM_DYN);
    cudaFuncSetAttribute(tc_gemm<EP_QK>,    cudaFuncAttributeMaxDynamicSharedMemorySize, SMEM_DYN);
    cudaFuncSetAttribute(tc_gemm<EP_VT>,    cudaFuncAttributeMaxDynamicSharedMemorySize, SMEM_DYN);
    cudaFuncSetAttribute(tc_gemm<EP_MERGE>, cudaFuncAttributeMaxDynamicSharedMemorySize, SMEM_DYN);
    cudaFuncSetAttribute(tc_gemm<EP_RES>,   cudaFuncAttributeMaxDynamicSharedMemorySize, SMEM_DYN);
    cudaFuncSetAttribute(tc_gemm<EP_GELU>,  cudaFuncAttributeMaxDynamicSharedMemorySize, SMEM_DYN);

    const float att_scale = 0.08838834764831845f; // 1/sqrt(128)

    // launch #1: input split; #2: fused weight prep
    split_kernel<<<(TOKENS*(size_t)EMBED + 1023)/1024, 256>>>(x, xhi, xlo, (size_t)TOKENS*EMBED);
    prep_weights<<<49152, 256>>>(Wq, Wk, Wv, Wo, W1, W2);

    // #3,#4,#5: QKV projections
    dim3 gQKV(EMBED/128, TOKENS/256, 1);
    tc_gemm<EP_QK><<<gQKV, 512, SMEM_DYN>>>(xhi, xlo, wqh, wql, bq, nullptr, qhi, qlo, TOKENS, EMBED, EMBED, 1.f, 0, 0);
    tc_gemm<EP_QK><<<gQKV, 512, SMEM_DYN>>>(xhi, xlo, wkh, wkl, bk, nullptr, khi, klo, TOKENS, EMBED, EMBED, 1.f, 0, 0);
    tc_gemm<EP_VT><<<gQKV, 512, SMEM_DYN>>>(xhi, xlo, wvh, wvl, bv, nullptr, vthi, vtlo, TOKENS, EMBED, EMBED, 1.f, 0, 0);

    // #6: scores = scale * Q @ K^T   <-- ncu -s 5 -c 1 profiles THIS launch
    dim3 gS(SEQ/128, SEQ/256, BATCH*HEADS);
    tc_gemm<EP_PLAIN><<<gS, 512, SMEM_DYN>>>(qhi, qlo, khi, klo, nullptr, nullptr, s, nullptr,
                                             SEQ, SEQ, HD, att_scale, (long)SEQ*HD, (long)SEQ*HD);
    softmax_kernel<<<BATCH*HEADS*SEQ, 256>>>(s, shi, slo);

    // O = P @ V^T
    dim3 gPV(1, SEQ/256, BATCH*HEADS);
    tc_gemm<EP_MERGE><<<gPV, 512, SMEM_DYN>>>(shi, slo, vthi, vtlo, nullptr, nullptr, aohi, aolo,
                                              SEQ, HD, SEQ, 1.f, (long)SEQ*SEQ, (long)HD*SEQ);

    // out-proj + residual, LN1
    dim3 gWo(EMBED/128, TOKENS/256, 1);
    tc_gemm<EP_RES><<<gWo, 512, SMEM_DYN>>>(aohi, aolo, woh, wol, bo, x, t1, nullptr,
                                            TOKENS, EMBED, EMBED, 1.f, 0, 0);
    ln_kernel<1><<<TOKENS, 256>>>(t1, g1, b1, h, hhi, hlo);

    // FFN
    dim3 gF1(DFF/128, TOKENS/256, 1);
    tc_gemm<EP_GELU><<<gF1, 512, SMEM_DYN>>>(hhi, hlo, w1h, w1l, bf1, nullptr, f1hi, f1lo,
                                             TOKENS, DFF, EMBED, 1.f, 0, 0);
    dim3 gF2(EMBED/128, TOKENS/256, 1);
    tc_gemm<EP_RES><<<gF2, 512, SMEM_DYN>>>(f1hi, f1lo, w2h, w2l, bf2, h, t1, nullptr,
                                            TOKENS, EMBED, DFF, 1.f, 0, 0);

    ln_kernel<0><<<TOKENS, 256>>>(t1, g2, b2, out, nullptr, nullptr);
}

// round 11
// speedup vs baseline: 1.2098x; 1.2098x over previous
#include <cuda_runtime.h>
#include <cuda_bf16.h>
#include <cuda_fp16.h>
#include <math.h>
#include <stdint.h>

#define EMBED 2048
#define HEADS 16
#define HD    128
#define DFF   8192
#define BATCH 2
#define SEQ   2048
#define TOKENS (BATCH*SEQ)
#define LN_EPS 1e-5f

typedef __nv_bfloat16 bf16;
typedef __half fp16;

// ---------------- scratch ----------------
__device__ __align__(1024) bf16 g_xhi[(size_t)TOKENS*EMBED], g_xlo[(size_t)TOKENS*EMBED];
__device__ __align__(1024) bf16 g_qhi[(size_t)TOKENS*EMBED], g_qlo[(size_t)TOKENS*EMBED];
__device__ __align__(1024) bf16 g_khi[(size_t)TOKENS*EMBED], g_klo[(size_t)TOKENS*EMBED];
__device__ __align__(1024) bf16 g_vthi[(size_t)TOKENS*EMBED], g_vtlo[(size_t)TOKENS*EMBED];
__device__ __align__(1024) float g_s [(size_t)BATCH*HEADS*SEQ*SEQ];
__device__ __align__(1024) bf16 g_shi[(size_t)BATCH*HEADS*SEQ*SEQ], g_slo[(size_t)BATCH*HEADS*SEQ*SEQ];
__device__ __align__(1024) bf16 g_aohi[(size_t)TOKENS*EMBED], g_aolo[(size_t)TOKENS*EMBED];
__device__ __align__(1024) float g_t1[(size_t)TOKENS*EMBED];
__device__ __align__(1024) float g_h [(size_t)TOKENS*EMBED];
__device__ __align__(1024) fp16 g_h16[(size_t)TOKENS*EMBED];        // LN1 out, fp16 single
__device__ __align__(1024) fp16 g_f116[(size_t)TOKENS*DFF];          // FFN hidden, fp16 single
__device__ __align__(1024) bf16 g_wqh[(size_t)EMBED*EMBED], g_wql[(size_t)EMBED*EMBED];
__device__ __align__(1024) bf16 g_wkh[(size_t)EMBED*EMBED], g_wkl[(size_t)EMBED*EMBED];
__device__ __align__(1024) bf16 g_wvh[(size_t)EMBED*EMBED], g_wvl[(size_t)EMBED*EMBED];
__device__ __align__(1024) bf16 g_woh[(size_t)EMBED*EMBED], g_wol[(size_t)EMBED*EMBED];
__device__ __align__(1024) fp16 g_w1h[(size_t)EMBED*DFF],   g_w1l[(size_t)EMBED*DFF];   // fp16 hi/lo
__device__ __align__(1024) fp16 g_w2h[(size_t)EMBED*DFF],   g_w2l[(size_t)EMBED*DFF];   // fp16 hi/lo

// ---------------- helpers ----------------
__device__ __forceinline__ uint32_t smem_u32(const void* p) {
    return (uint32_t)__cvta_generic_to_shared(p);
}
__device__ __forceinline__ void cp16(uint32_t dst, const void* src) {
    asm volatile("cp.async.cg.shared.global [%0], [%1], 16;\n" :: "r"(dst), "l"(src));
}
__device__ __forceinline__ void cp_commit() { asm volatile("cp.async.commit_group;\n"); }
template<int Ngrp> __device__ __forceinline__ void cp_wait() {
    asm volatile("cp.async.wait_group %0;\n" :: "n"(Ngrp));
}
__device__ __forceinline__ void ldsm4(uint32_t* r, uint32_t addr) {
    asm volatile("ldmatrix.sync.aligned.m8n8.x4.shared.b16 {%0,%1,%2,%3}, [%4];"
                 : "=r"(r[0]), "=r"(r[1]), "=r"(r[2]), "=r"(r[3]) : "r"(addr));
}
__device__ __forceinline__ void mma16816(float* c, const uint32_t* a, const uint32_t* b) {
    asm volatile(
        "mma.sync.aligned.m16n8k16.row.col.f32.bf16.bf16.f32 "
        "{%0,%1,%2,%3}, {%4,%5,%6,%7}, {%8,%9}, {%0,%1,%2,%3};\n"
        : "+f"(c[0]), "+f"(c[1]), "+f"(c[2]), "+f"(c[3])
        : "r"(a[0]), "r"(a[1]), "r"(a[2]), "r"(a[3]), "r"(b[0]), "r"(b[1]));
}
__device__ __forceinline__ void mma16816h(float* c, const uint32_t* a, const uint32_t* b) {
    asm volatile(
        "mma.sync.aligned.m16n8k16.row.col.f32.f16.f16.f32 "
        "{%0,%1,%2,%3}, {%4,%5,%6,%7}, {%8,%9}, {%0,%1,%2,%3};\n"
        : "+f"(c[0]), "+f"(c[1]), "+f"(c[2]), "+f"(c[3])
        : "r"(a[0]), "r"(a[1]), "r"(a[2]), "r"(a[3]), "r"(b[0]), "r"(b[1]));
}
__device__ __forceinline__ uint32_t swz(uint32_t off) { return off ^ ((off >> 3) & 0x70); }

__device__ __forceinline__ void split_write(bf16* hi, bf16* lo, size_t o, float v) {
    bf16 h = __float2bfloat16(v);
    hi[o] = h;
    lo[o] = __float2bfloat16(v - __bfloat162float(h));
}
__device__ __forceinline__ void split_write_h(fp16* hi, fp16* lo, size_t o, float v) {
    fp16 h = __float2half(v);
    hi[o] = h;
    lo[o] = __float2half(v - __half2float(h));
}

// ---------------- fused weight prep (Wq/Wk/Wv/Wo -> bf16 hi/lo; W1/W2 -> fp16 hi/lo) ----------------
__global__ __launch_bounds__(256)
void prep_weights(const float* __restrict__ Wq, const float* __restrict__ Wk,
                  const float* __restrict__ Wv, const float* __restrict__ Wo,
                  const float* __restrict__ W1, const float* __restrict__ W2)
{
    __shared__ float t[32][33];
    const int bidx = blockIdx.x;

    const float* in; int R, C, tbase, isfp16;
    bf16 *hib = nullptr, *lob = nullptr;
    fp16 *hih = nullptr, *loh = nullptr;
    if (bidx < 16384) {
        R = EMBED; C = EMBED; isfp16 = 0;
        if (bidx < 4096)       { in = Wq; hib = g_wqh; lob = g_wql; tbase = 0; }
        else if (bidx < 8192)  { in = Wk; hib = g_wkh; lob = g_wkl; tbase = 4096; }
        else if (bidx < 12288) { in = Wv; hib = g_wvh; lob = g_wvl; tbase = 8192; }
        else                   { in = Wo; hib = g_woh; lob = g_wol; tbase = 12288; }
    } else if (bidx < 32768) {
        in = W1; hih = g_w1h; loh = g_w1l; R = EMBED; C = DFF; tbase = 16384; isfp16 = 1;
    } else {
        in = W2; hih = g_w2h; loh = g_w2l; R = DFF; C = EMBED; tbase = 32768; isfp16 = 1;
    }
    const int t0 = bidx - tbase;
    const int tiles_x = C >> 5;
    const int c0 = (t0 % tiles_x) << 5;
    const int r0 = (t0 / tiles_x) << 5;

    const int tx = threadIdx.x & 31, ty = threadIdx.x >> 5;
    #pragma unroll
    for (int i = 0; i < 32; i += 8)
        t[ty + i][tx] = in[(size_t)(r0 + ty + i) * C + c0 + tx];
    __syncthreads();
    #pragma unroll
    for (int i = 0; i < 32; i += 8) {
        const size_t o = (size_t)(c0 + ty + i) * R + r0 + tx;
        const float v = t[tx][ty + i];
        if (isfp16) split_write_h(hih, loh, o, v);
        else        split_write(hib, lob, o, v);
    }
}

// ---------------- elementwise fp32 -> bf16 hi/lo ----------------
__global__ __launch_bounds__(256)
void split_kernel(const float* __restrict__ in, bf16* __restrict__ hi, bf16* __restrict__ lo, size_t n)
{
    size_t i = (size_t)blockIdx.x * 1024 + threadIdx.x;
    #pragma unroll
    for (int j = 0; j < 4; j++) {
        size_t o = i + (size_t)j * 256;
        if (o < n) split_write(hi, lo, o, in[o]);
    }
}

// ---------------- bf16x3 mma.sync GEMM (attention path; unchanged numerics) ----------------
// CTA tile 256x128, 16 warps (512 thr) of 64x32, K-chunk 64, double buffered.
enum { EP_PLAIN=0, EP_QK=1, EP_VT=2, EP_MERGE=3, EP_RES=4 };

#define ST_AH 0
#define ST_AL 32768
#define ST_BH 65536
#define ST_BL 81920
#define STAGE 98304
#define SMEM_DYN (2*STAGE + 1024)

template<int MODE>
__global__ __launch_bounds__(512)
void tc_gemm(const bf16* __restrict__ Ahi, const bf16* __restrict__ Alo,
             const bf16* __restrict__ Bhi, const bf16* __restrict__ Blo,
             const float* __restrict__ bias, const float* __restrict__ res,
             void* __restrict__ O0, void* __restrict__ O1,
             int M, int N, int K, float scale, long sA, long sB)
{
    extern __shared__ char dsm[];
    const uint32_t tile0 = (smem_u32(dsm) + 1023u) & ~1023u;

    const int tid = threadIdx.x, warp = tid >> 5, lane = tid & 31;
    const int wm = warp >> 2;       // 0..3 -> m offset 64
    const int wn = warp & 3;        // 0..3 -> n offset 32
    const int bz = blockIdx.z;
    const int bm = blockIdx.y * 256, bn = blockIdx.x * 128;

    const bf16* Ah_g = Ahi + (size_t)bz * sA;
    const bf16* Al_g = Alo + (size_t)bz * sA;
    const bf16* Bh_g = Bhi + (size_t)bz * sB;
    const bf16* Bl_g = Blo + (size_t)bz * sB;

    float acc[4][4][4];
    #pragma unroll
    for (int i = 0; i < 4; i++)
        #pragma unroll
        for (int j = 0; j < 4; j++)
            #pragma unroll
            for (int p = 0; p < 4; p++) acc[i][j][p] = 0.f;

    const int NIT = K >> 6;

    auto load_chunk = [&](int stage, int k0) {
        const uint32_t st = tile0 + (uint32_t)stage * STAGE;
        #pragma unroll
        for (int i = 0; i < 4; i++) {
            const int idx = i * 512 + tid;
            const int r = idx >> 3, c = idx & 7;
            const uint32_t so = swz((uint32_t)(r * 128 + c * 16));
            cp16(st + ST_AH + so, Ah_g + (size_t)(bm + r) * K + k0 + c * 8);
            cp16(st + ST_AL + so, Al_g + (size_t)(bm + r) * K + k0 + c * 8);
        }
        #pragma unroll
        for (int i = 0; i < 2; i++) {
            const int idx = i * 512 + tid;
            const int r = idx >> 3, c = idx & 7;
            const uint32_t so = swz((uint32_t)(r * 128 + c * 16));
            cp16(st + ST_BH + so, Bh_g + (size_t)(bn + r) * K + k0 + c * 8);
            cp16(st + ST_BL + so, Bl_g + (size_t)(bn + r) * K + k0 + c * 8);
        }
        cp_commit();
    };

    load_chunk(0, 0);
    if (NIT > 1) load_chunk(1, 64);

    const uint32_t lrow = lane & 15;
    const uint32_t lkb  = (lane >> 4) * 16;

    for (int it = 0; it < NIT; it++) {
        const int cur = it & 1;
        if (it + 1 < NIT) cp_wait<1>(); else cp_wait<0>();
        __syncthreads();

        const uint32_t st = tile0 + (uint32_t)cur * STAGE;

        #pragma unroll
        for (int ks = 0; ks < 4; ks++) {
            const uint32_t kb = (uint32_t)ks * 32 + lkb;

            uint32_t ah[4][4];
            #pragma unroll
            for (int mt = 0; mt < 4; mt++)
                ldsm4(ah[mt], st + ST_AH + swz((uint32_t)((wm*64 + mt*16 + lrow) * 128) + kb));

            uint32_t bh[2][4], bl[2][4];
            #pragma unroll
            for (int g = 0; g < 2; g++) {
                const uint32_t so = swz((uint32_t)((wn*32 + g*16 + lrow) * 128) + kb);
                ldsm4(bh[g], st + ST_BH + so);
                ldsm4(bl[g], st + ST_BL + so);
            }

            #pragma unroll
            for (int mt = 0; mt < 4; mt++)
                #pragma unroll
                for (int nt = 0; nt < 4; nt++) {
                    const int g = nt >> 1, s2 = nt & 1;
                    uint32_t bf2r[2] = { bh[g][s2], bh[g][s2 + 2] };
                    mma16816(acc[mt][nt], ah[mt], bf2r);
                }
            #pragma unroll
            for (int mt = 0; mt < 4; mt++)
                #pragma unroll
                for (int nt = 0; nt < 4; nt++) {
                    const int g = nt >> 1, s2 = nt & 1;
                    uint32_t bf2r[2] = { bl[g][s2], bl[g][s2 + 2] };
                    mma16816(acc[mt][nt], ah[mt], bf2r);
                }
            uint32_t al[4][4];
            #pragma unroll
            for (int mt = 0; mt < 4; mt++)
                ldsm4(al[mt], st + ST_AL + swz((uint32_t)((wm*64 + mt*16 + lrow) * 128) + kb));
            #pragma unroll
            for (int mt = 0; mt < 4; mt++)
                #pragma unroll
                for (int nt = 0; nt < 4; nt++) {
                    const int g = nt >> 1, s2 = nt & 1;
                    uint32_t bf2r[2] = { bh[g][s2], bh[g][s2 + 2] };
                    mma16816(acc[mt][nt], al[mt], bf2r);
                }
        }
        __syncthreads();
        if (it + 2 < NIT) load_chunk(cur, (it + 2) * 64);
    }

    // ---- epilogue ----
    #pragma unroll
    for (int mt = 0; mt < 4; mt++) {
        const int m0 = bm + wm * 64 + mt * 16 + (lane >> 2);
        #pragma unroll
        for (int nt = 0; nt < 4; nt++) {
            const int n0 = bn + wn * 32 + nt * 8 + (lane & 3) * 2;
            #pragma unroll
            for (int i = 0; i < 4; i++) {
                const int m = m0 + ((i >= 2) ? 8 : 0);
                const int n = n0 + (i & 1);
                float v = acc[mt][nt][i] * scale;

                if (MODE == EP_PLAIN) {
                    ((float*)O0)[(size_t)bz * ((size_t)M * N) + (size_t)m * N + n] = v;
                } else if (MODE == EP_QK) {
                    v += bias[n];
                    const int b = m >> 11, nn = m & (SEQ - 1);
                    const int h = n >> 7,  d = n & (HD - 1);
                    split_write((bf16*)O0, (bf16*)O1,
                                (((size_t)(b * HEADS + h)) * SEQ + nn) * HD + d, v);
                } else if (MODE == EP_VT) {
                    v += bias[n];
                    const int b = m >> 11, nn = m & (SEQ - 1);
                    const int h = n >> 7,  d = n & (HD - 1);
                    split_write((bf16*)O0, (bf16*)O1,
                                (((size_t)(b * HEADS + h)) * HD + d) * SEQ + nn, v);
                } else if (MODE == EP_MERGE) {
                    const int b = bz >> 4, h = bz & 15;
                    split_write((bf16*)O0, (bf16*)O1,
                                ((size_t)(b * SEQ + m)) * EMBED + h * HD + n, v);
                } else { // EP_RES
                    v += bias[n] + res[(size_t)m * N + n];
                    ((float*)O0)[(size_t)m * N + n] = v;
                }
            }
        }
    }
}

// ---------------- fp16x2 mma.sync GEMM (FFN path) ----------------
// D = A(fp16) @ (Bhi+Blo)^T + bias;  2 MMAs per fragment.
// CTA tile 256x128, 16 warps of 64x32, K-chunk 64, double buffered.
enum { H2_GELU=0, H2_RES=1 };

#define H2_A  0
#define H2_BH 32768
#define H2_BL 49152
#define H2_STAGE 65536
#define SMEM_DYN_H2 (2*H2_STAGE + 1024)

template<int MODE>
__global__ __launch_bounds__(512)
void tc_gemm_h2(const fp16* __restrict__ A,
                const fp16* __restrict__ Bhi, const fp16* __restrict__ Blo,
                const float* __restrict__ bias, const float* __restrict__ res,
                void* __restrict__ O0, int M, int N, int K)
{
    extern __shared__ char dsm[];
    const uint32_t tile0 = (smem_u32(dsm) + 1023u) & ~1023u;

    const int tid = threadIdx.x, warp = tid >> 5, lane = tid & 31;
    const int wm = warp >> 2, wn = warp & 3;
    const int bm = blockIdx.y * 256, bn = blockIdx.x * 128;

    float acc[4][4][4];
    #pragma unroll
    for (int i = 0; i < 4; i++)
        #pragma unroll
        for (int j = 0; j < 4; j++)
            #pragma unroll
            for (int p = 0; p < 4; p++) acc[i][j][p] = 0.f;

    const int NIT = K >> 6;

    auto load_chunk = [&](int stage, int k0) {
        const uint32_t st = tile0 + (uint32_t)stage * H2_STAGE;
        #pragma unroll
        for (int i = 0; i < 4; i++) {
            const int idx = i * 512 + tid;
            const int r = idx >> 3, c = idx & 7;
            const uint32_t so = swz((uint32_t)(r * 128 + c * 16));
            cp16(st + H2_A + so, A + (size_t)(bm + r) * K + k0 + c * 8);
        }
        #pragma unroll
        for (int i = 0; i < 2; i++) {
            const int idx = i * 512 + tid;
            const int r = idx >> 3, c = idx & 7;
            const uint32_t so = swz((uint32_t)(r * 128 + c * 16));
            cp16(st + H2_BH + so, Bhi + (size_t)(bn + r) * K + k0 + c * 8);
            cp16(st + H2_BL + so, Blo + (size_t)(bn + r) * K + k0 + c * 8);
        }
        cp_commit();
    };

    load_chunk(0, 0);
    if (NIT > 1) load_chunk(1, 64);

    const uint32_t lrow = lane & 15;
    const uint32_t lkb  = (lane >> 4) * 16;

    for (int it = 0; it < NIT; it++) {
        const int cur = it & 1;
        if (it + 1 < NIT) cp_wait<1>(); else cp_wait<0>();
        __syncthreads();

        const uint32_t st = tile0 + (uint32_t)cur * H2_STAGE;

        #pragma unroll
        for (int ks = 0; ks < 4; ks++) {
            const uint32_t kb = (uint32_t)ks * 32 + lkb;

            uint32_t ah[4][4];
            #pragma unroll
            for (int mt = 0; mt < 4; mt++)
                ldsm4(ah[mt], st + H2_A + swz((uint32_t)((wm*64 + mt*16 + lrow) * 128) + kb));

            uint32_t bh[2][4], bl[2][4];
            #pragma unroll
            for (int g = 0; g < 2; g++) {
                const uint32_t so = swz((uint32_t)((wn*32 + g*16 + lrow) * 128) + kb);
                ldsm4(bh[g], st + H2_BH + so);
                ldsm4(bl[g], st + H2_BL + so);
            }

            #pragma unroll
            for (int mt = 0; mt < 4; mt++)
                #pragma unroll
                for (int nt = 0; nt < 4; nt++) {
                    const int g = nt >> 1, s2 = nt & 1;
                    uint32_t bf2r[2] = { bh[g][s2], bh[g][s2 + 2] };
                    mma16816h(acc[mt][nt], ah[mt], bf2r);
                }
            #pragma unroll
            for (int mt = 0; mt < 4; mt++)
                #pragma unroll
                for (int nt = 0; nt < 4; nt++) {
                    const int g = nt >> 1, s2 = nt & 1;
                    uint32_t bf2r[2] = { bl[g][s2], bl[g][s2 + 2] };
                    mma16816h(acc[mt][nt], ah[mt], bf2r);
                }
        }
        __syncthreads();
        if (it + 2 < NIT) load_chunk(cur, (it + 2) * 64);
    }

    // ---- epilogue ----
    #pragma unroll
    for (int mt = 0; mt < 4; mt++) {
        const int m0 = bm + wm * 64 + mt * 16 + (lane >> 2);
        #pragma unroll
        for (int nt = 0; nt < 4; nt++) {
            const int n0 = bn + wn * 32 + nt * 8 + (lane & 3) * 2;
            #pragma unroll
            for (int i = 0; i < 4; i++) {
                const int m = m0 + ((i >= 2) ? 8 : 0);
                const int n = n0 + (i & 1);
                float v = acc[mt][nt][i] + bias[n];
                if (MODE == H2_GELU) {
                    v = 0.5f * v * (1.f + erff(v * 0.70710678118654752f));
                    ((fp16*)O0)[(size_t)m * N + n] = __float2half(v);
                } else { // H2_RES
                    v += res[(size_t)m * N + n];
                    ((float*)O0)[(size_t)m * N + n] = v;
                }
            }
        }
    }
}

// ---------------- softmax: fp32 in -> hi/lo bf16 out ----------------
__global__ __launch_bounds__(256)
void softmax_kernel(const float* __restrict__ S, bf16* __restrict__ Phi, bf16* __restrict__ Plo)
{
    __shared__ float red[256];
    const size_t row = blockIdx.x;
    const float* p = S + row * (size_t)SEQ;
    const int tid = threadIdx.x;

    float v[8];
    float lmax = -1e30f;
    #pragma unroll
    for (int i = 0; i < 8; i++) { v[i] = p[tid + i*256]; lmax = fmaxf(lmax, v[i]); }
    red[tid] = lmax; __syncthreads();
    for (int s = 128; s > 0; s >>= 1) { if (tid < s) red[tid] = fmaxf(red[tid], red[tid+s]); __syncthreads(); }
    const float m = red[0]; __syncthreads();

    float lsum = 0.f;
    #pragma unroll
    for (int i = 0; i < 8; i++) { v[i] = expf(v[i] - m); lsum += v[i]; }
    red[tid] = lsum; __syncthreads();
    for (int s = 128; s > 0; s >>= 1) { if (tid < s) red[tid] += red[tid+s]; __syncthreads(); }
    const float inv = 1.f / red[0];

    #pragma unroll
    for (int i = 0; i < 8; i++)
        split_write(Phi, Plo, row * (size_t)SEQ + tid + i*256, v[i] * inv);
}

// ---------------- LayerNorm ----------------
// H16=1: also write fp16 copy (for FFN input)
template<int H16>
__global__ __launch_bounds__(256)
void ln_kernel(const float* __restrict__ in, const float* __restrict__ g,
               const float* __restrict__ b, float* __restrict__ outf,
               fp16* __restrict__ o16)
{
    __shared__ float r1[256], r2[256];
    const size_t row = blockIdx.x;
    const float* p = in + row * (size_t)EMBED;
    const int tid = threadIdx.x;

    float v[8];
    float s = 0.f, ss = 0.f;
    #pragma unroll
    for (int i = 0; i < 8; i++) { v[i] = p[tid + i*256]; s += v[i]; ss += v[i]*v[i]; }
    r1[tid] = s; r2[tid] = ss; __syncthreads();
    for (int st = 128; st > 0; st >>= 1) {
        if (tid < st) { r1[tid] += r1[tid+st]; r2[tid] += r2[tid+st]; }
        __syncthreads();
    }
    const float mu  = r1[0] * (1.f / EMBED);
    const float var = r2[0] * (1.f / EMBED) - mu * mu;
    const float rs  = rsqrtf(var + LN_EPS);

    #pragma unroll
    for (int i = 0; i < 8; i++) {
        const int c = tid + i*256;
        const float o = (v[i] - mu) * rs * g[c] + b[c];
        outf[row * (size_t)EMBED + c] = o;
        if (H16) o16[row * (size_t)EMBED + c] = __float2half(o);
    }
}

// ---------------- launch ----------------
extern "C" void kernel_launch(void* const* d_in, const int* in_sizes, int n_in,
                              void* d_out, int out_size)
{
    const float* x   = (const float*)d_in[0];
    const float* Wq  = (const float*)d_in[1];
    const float* bq  = (const float*)d_in[2];
    const float* Wk  = (const float*)d_in[3];
    const float* bk  = (const float*)d_in[4];
    const float* Wv  = (const float*)d_in[5];
    const float* bv  = (const float*)d_in[6];
    const float* Wo  = (const float*)d_in[7];
    const float* bo  = (const float*)d_in[8];
    const float* g1  = (const float*)d_in[9];
    const float* b1  = (const float*)d_in[10];
    const float* g2  = (const float*)d_in[11];
    const float* b2  = (const float*)d_in[12];
    const float* W1  = (const float*)d_in[13];
    const float* bf1 = (const float*)d_in[14];
    const float* W2  = (const float*)d_in[15];
    const float* bf2 = (const float*)d_in[16];
    float* out = (float*)d_out;

    bf16 *xhi,*xlo,*qhi,*qlo,*khi,*klo,*vthi,*vtlo,*shi,*slo,*aohi,*aolo;
    bf16 *wqh,*wql,*wkh,*wkl,*wvh,*wvl,*woh,*wol;
    fp16 *h16,*f116,*w1h,*w1l,*w2h,*w2l;
    float *s, *t1, *h;
    cudaGetSymbolAddress((void**)&xhi, g_xhi); cudaGetSymbolAddress((void**)&xlo, g_xlo);
    cudaGetSymbolAddress((void**)&qhi, g_qhi); cudaGetSymbolAddress((void**)&qlo, g_qlo);
    cudaGetSymbolAddress((void**)&khi, g_khi); cudaGetSymbolAddress((void**)&klo, g_klo);
    cudaGetSymbolAddress((void**)&vthi,g_vthi);cudaGetSymbolAddress((void**)&vtlo,g_vtlo);
    cudaGetSymbolAddress((void**)&s,   g_s);
    cudaGetSymbolAddress((void**)&shi, g_shi); cudaGetSymbolAddress((void**)&slo, g_slo);
    cudaGetSymbolAddress((void**)&aohi,g_aohi);cudaGetSymbolAddress((void**)&aolo,g_aolo);
    cudaGetSymbolAddress((void**)&t1,  g_t1);  cudaGetSymbolAddress((void**)&h,   g_h);
    cudaGetSymbolAddress((void**)&h16, g_h16); cudaGetSymbolAddress((void**)&f116,g_f116);
    cudaGetSymbolAddress((void**)&wqh, g_wqh); cudaGetSymbolAddress((void**)&wql, g_wql);
    cudaGetSymbolAddress((void**)&wkh, g_wkh); cudaGetSymbolAddress((void**)&wkl, g_wkl);
    cudaGetSymbolAddress((void**)&wvh, g_wvh); cudaGetSymbolAddress((void**)&wvl, g_wvl);
    cudaGetSymbolAddress((void**)&woh, g_woh); cudaGetSymbolAddress((void**)&wol, g_wol);
    cudaGetSymbolAddress((void**)&w1h, g_w1h); cudaGetSymbolAddress((void**)&w1l, g_w1l);
    cudaGetSymbolAddress((void**)&w2h, g_w2h); cudaGetSymbolAddress((void**)&w2l, g_w2l);

    cudaFuncSetAttribute(tc_gemm<EP_PLAIN>, cudaFuncAttributeMaxDynamicSharedMemorySize, SMEM_DYN);
    cudaFuncSetAttribute(tc_gemm<EP_QK>,    cudaFuncAttributeMaxDynamicSharedMemorySize, SMEM_DYN);
    cudaFuncSetAttribute(tc_gemm<EP_VT>,    cudaFuncAttributeMaxDynamicSharedMemorySize, SMEM_DYN);
    cudaFuncSetAttribute(tc_gemm<EP_MERGE>, cudaFuncAttributeMaxDynamicSharedMemorySize, SMEM_DYN);
    cudaFuncSetAttribute(tc_gemm<EP_RES>,   cudaFuncAttributeMaxDynamicSharedMemorySize, SMEM_DYN);
    cudaFuncSetAttribute(tc_gemm_h2<H2_GELU>, cudaFuncAttributeMaxDynamicSharedMemorySize, SMEM_DYN_H2);
    cudaFuncSetAttribute(tc_gemm_h2<H2_RES>,  cudaFuncAttributeMaxDynamicSharedMemorySize, SMEM_DYN_H2);

    const float att_scale = 0.08838834764831845f; // 1/sqrt(128)

    // launch #1: input split; #2: fused weight prep
    split_kernel<<<(TOKENS*(size_t)EMBED + 1023)/1024, 256>>>(x, xhi, xlo, (size_t)TOKENS*EMBED);
    prep_weights<<<49152, 256>>>(Wq, Wk, Wv, Wo, W1, W2);

    // QKV projections (bf16x3)
    dim3 gQKV(EMBED/128, TOKENS/256, 1);
    tc_gemm<EP_QK><<<gQKV, 512, SMEM_DYN>>>(xhi, xlo, wqh, wql, bq, nullptr, qhi, qlo, TOKENS, EMBED, EMBED, 1.f, 0, 0);
    tc_gemm<EP_QK><<<gQKV, 512, SMEM_DYN>>>(xhi, xlo, wkh, wkl, bk, nullptr, khi, klo, TOKENS, EMBED, EMBED, 1.f, 0, 0);
    tc_gemm<EP_VT><<<gQKV, 512, SMEM_DYN>>>(xhi, xlo, wvh, wvl, bv, nullptr, vthi, vtlo, TOKENS, EMBED, EMBED, 1.f, 0, 0);

    // scores = scale * Q @ K^T
    dim3 gS(SEQ/128, SEQ/256, BATCH*HEADS);
    tc_gemm<EP_PLAIN><<<gS, 512, SMEM_DYN>>>(qhi, qlo, khi, klo, nullptr, nullptr, s, nullptr,
                                             SEQ, SEQ, HD, att_scale, (long)SEQ*HD, (long)SEQ*HD);
    softmax_kernel<<<BATCH*HEADS*SEQ, 256>>>(s, shi, slo);

    // O = P @ V^T
    dim3 gPV(1, SEQ/256, BATCH*HEADS);
    tc_gemm<EP_MERGE><<<gPV, 512, SMEM_DYN>>>(shi, slo, vthi, vtlo, nullptr, nullptr, aohi, aolo,
                                              SEQ, HD, SEQ, 1.f, (long)SEQ*SEQ, (long)HD*SEQ);

    // out-proj + residual, LN1 (fp16 copy of h for FFN)
    dim3 gWo(EMBED/128, TOKENS/256, 1);
    tc_gemm<EP_RES><<<gWo, 512, SMEM_DYN>>>(aohi, aolo, woh, wol, bo, x, t1, nullptr,
                                            TOKENS, EMBED, EMBED, 1.f, 0, 0);
    ln_kernel<1><<<TOKENS, 256>>>(t1, g1, b1, h, h16);

    // FFN (fp16x2)
    dim3 gF1(DFF/128, TOKENS/256, 1);
    tc_gemm_h2<H2_GELU><<<gF1, 512, SMEM_DYN_H2>>>(h16, w1h, w1l, bf1, nullptr, f116,
                                                   TOKENS, DFF, EMBED);
    dim3 gF2(EMBED/128, TOKENS/256, 1);
    tc_gemm_h2<H2_RES><<<gF2, 512, SMEM_DYN_H2>>>(f116, w2h, w2l, bf2, h, t1,
                                                  TOKENS, EMBED, DFF);

    ln_kernel<0><<<TOKENS, 256>>>(t1, g2, b2, out, nullptr);
}

// round 14
// speedup vs baseline: 1.4495x; 1.1981x over previous
#include <cuda_runtime.h>
#include <cuda_fp16.h>
#include <math.h>
#include <stdint.h>

#define EMBED 2048
#define HEADS 16
#define HD    128
#define DFF   8192
#define BATCH 2
#define SEQ   2048
#define TOKENS (BATCH*SEQ)
#define LN_EPS 1e-5f

typedef __half fp16;

// ---------------- scratch ----------------
// NOTE: f116/h16 alias into g_s (dead after softmax); ao16 aliases g_q16 (dead after scores).
__device__ __align__(1024) fp16 g_x16[(size_t)TOKENS*EMBED];
__device__ __align__(1024) fp16 g_q16[(size_t)TOKENS*EMBED];                                // also ao16
__device__ __align__(1024) fp16 g_khi[(size_t)TOKENS*EMBED], g_klo[(size_t)TOKENS*EMBED];   // [B,H,N,hd]
__device__ __align__(1024) fp16 g_vthi[(size_t)TOKENS*EMBED], g_vtlo[(size_t)TOKENS*EMBED]; // [B,H,hd,N]
__device__ __align__(1024) float g_s [(size_t)BATCH*HEADS*SEQ*SEQ];                         // also f116,h16
__device__ __align__(1024) fp16 g_p16[(size_t)BATCH*HEADS*SEQ*SEQ];
__device__ __align__(1024) float g_t1[(size_t)TOKENS*EMBED];
__device__ __align__(1024) float g_h [(size_t)TOKENS*EMBED];
__device__ __align__(1024) fp16 g_wqh[(size_t)EMBED*EMBED], g_wql[(size_t)EMBED*EMBED];
__device__ __align__(1024) fp16 g_wkh[(size_t)EMBED*EMBED], g_wkl[(size_t)EMBED*EMBED];
__device__ __align__(1024) fp16 g_wvh[(size_t)EMBED*EMBED], g_wvl[(size_t)EMBED*EMBED];
__device__ __align__(1024) fp16 g_woh[(size_t)EMBED*EMBED], g_wol[(size_t)EMBED*EMBED];
__device__ __align__(1024) fp16 g_w1h[(size_t)EMBED*DFF],   g_w1l[(size_t)EMBED*DFF];
__device__ __align__(1024) fp16 g_w2h[(size_t)EMBED*DFF],   g_w2l[(size_t)EMBED*DFF];

// ---------------- helpers ----------------
__device__ __forceinline__ uint32_t smem_u32(const void* p) {
    return (uint32_t)__cvta_generic_to_shared(p);
}
__device__ __forceinline__ void cp16(uint32_t dst, const void* src) {
    asm volatile("cp.async.cg.shared.global [%0], [%1], 16;\n" :: "r"(dst), "l"(src));
}
__device__ __forceinline__ void cp_commit() { asm volatile("cp.async.commit_group;\n"); }
template<int Ngrp> __device__ __forceinline__ void cp_wait() {
    asm volatile("cp.async.wait_group %0;\n" :: "n"(Ngrp));
}
__device__ __forceinline__ void ldsm4(uint32_t* r, uint32_t addr) {
    asm volatile("ldmatrix.sync.aligned.m8n8.x4.shared.b16 {%0,%1,%2,%3}, [%4];"
                 : "=r"(r[0]), "=r"(r[1]), "=r"(r[2]), "=r"(r[3]) : "r"(addr));
}
__device__ __forceinline__ void mma16816h(float* c, const uint32_t* a, const uint32_t* b) {
    asm volatile(
        "mma.sync.aligned.m16n8k16.row.col.f32.f16.f16.f32 "
        "{%0,%1,%2,%3}, {%4,%5,%6,%7}, {%8,%9}, {%0,%1,%2,%3};\n"
        : "+f"(c[0]), "+f"(c[1]), "+f"(c[2]), "+f"(c[3])
        : "r"(a[0]), "r"(a[1]), "r"(a[2]), "r"(a[3]), "r"(b[0]), "r"(b[1]));
}
__device__ __forceinline__ uint32_t swz(uint32_t off) { return off ^ ((off >> 3) & 0x70); }

__device__ __forceinline__ void split_write_h(fp16* hi, fp16* lo, size_t o, float v) {
    fp16 h = __float2half(v);
    hi[o] = h;
    lo[o] = __float2half(v - __half2float(h));
}

// ---------------- fused weight prep: all -> fp16 hi/lo, transposed ----------------
__global__ __launch_bounds__(256)
void prep_weights(const float* __restrict__ Wq, const float* __restrict__ Wk,
                  const float* __restrict__ Wv, const float* __restrict__ Wo,
                  const float* __restrict__ W1, const float* __restrict__ W2)
{
    __shared__ float t[32][33];
    const int bidx = blockIdx.x;

    const float* in; fp16 *hi, *lo; int R, C, tbase;
    if (bidx < 16384) {
        R = EMBED; C = EMBED;
        if (bidx < 4096)       { in = Wq; hi = g_wqh; lo = g_wql; tbase = 0; }
        else if (bidx < 8192)  { in = Wk; hi = g_wkh; lo = g_wkl; tbase = 4096; }
        else if (bidx < 12288) { in = Wv; hi = g_wvh; lo = g_wvl; tbase = 8192; }
        else                   { in = Wo; hi = g_woh; lo = g_wol; tbase = 12288; }
    } else if (bidx < 32768) {
        in = W1; hi = g_w1h; lo = g_w1l; R = EMBED; C = DFF; tbase = 16384;
    } else {
        in = W2; hi = g_w2h; lo = g_w2l; R = DFF; C = EMBED; tbase = 32768;
    }
    const int t0 = bidx - tbase;
    const int tiles_x = C >> 5;
    const int c0 = (t0 % tiles_x) << 5;
    const int r0 = (t0 / tiles_x) << 5;

    const int tx = threadIdx.x & 31, ty = threadIdx.x >> 5;
    #pragma unroll
    for (int i = 0; i < 32; i += 8)
        t[ty + i][tx] = in[(size_t)(r0 + ty + i) * C + c0 + tx];
    __syncthreads();
    #pragma unroll
    for (int i = 0; i < 32; i += 8)
        split_write_h(hi, lo, (size_t)(c0 + ty + i) * R + r0 + tx, t[tx][ty + i]);
}

// ---------------- elementwise fp32 -> fp16 ----------------
__global__ __launch_bounds__(256)
void cvt16_kernel(const float* __restrict__ in, fp16* __restrict__ o, size_t n)
{
    size_t i = (size_t)blockIdx.x * 1024 + threadIdx.x;
    #pragma unroll
    for (int j = 0; j < 4; j++) {
        size_t off = i + (size_t)j * 256;
        if (off < n) o[off] = __float2half(in[off]);
    }
}

// ---------------- fp16x2 mma.sync GEMM (all GEMMs) ----------------
// D = scale * A(fp16) @ (Bhi+Blo)^T (+bias/epilogue); 2 MMAs per fragment.
// CTA tile 256x128, 16 warps (512 thr) of 64x32, K-chunk 64, double buffered.
enum { EP_PLAIN=0, EP_Q16=1, EP_K=2, EP_VT=3, EP_MERGE16=4, EP_RES=5, EP_GELU=6 };

#define H2_A  0
#define H2_BH 32768
#define H2_BL 49152
#define H2_STAGE 65536
#define SMEM_DYN_H2 (2*H2_STAGE + 1024)

template<int MODE>
__global__ __launch_bounds__(512)
void hgemm(const fp16* __restrict__ A,
           const fp16* __restrict__ Bhi, const fp16* __restrict__ Blo,
           const float* __restrict__ bias, const float* __restrict__ res,
           void* __restrict__ O0, void* __restrict__ O1,
           int M, int N, int K, float scale, long sA, long sB)
{
    extern __shared__ char dsm[];
    const uint32_t tile0 = (smem_u32(dsm) + 1023u) & ~1023u;

    const int tid = threadIdx.x, warp = tid >> 5, lane = tid & 31;
    const int wm = warp >> 2;       // 0..3 -> m offset 64
    const int wn = warp & 3;        // 0..3 -> n offset 32
    const int bz = blockIdx.z;
    const int bm = blockIdx.y * 256, bn = blockIdx.x * 128;

    const fp16* A_g  = A   + (size_t)bz * sA;
    const fp16* Bh_g = Bhi + (size_t)bz * sB;
    const fp16* Bl_g = Blo + (size_t)bz * sB;

    float acc[4][4][4];
    #pragma unroll
    for (int i = 0; i < 4; i++)
        #pragma unroll
        for (int j = 0; j < 4; j++)
            #pragma unroll
            for (int p = 0; p < 4; p++) acc[i][j][p] = 0.f;

    const int NIT = K >> 6;

    auto load_chunk = [&](int stage, int k0) {
        const uint32_t st = tile0 + (uint32_t)stage * H2_STAGE;
        #pragma unroll
        for (int i = 0; i < 4; i++) {              // A: 256 rows x 8 x 16B
            const int idx = i * 512 + tid;
            const int r = idx >> 3, c = idx & 7;
            const uint32_t so = swz((uint32_t)(r * 128 + c * 16));
            cp16(st + H2_A + so, A_g + (size_t)(bm + r) * K + k0 + c * 8);
        }
        #pragma unroll
        for (int i = 0; i < 2; i++) {              // B hi/lo: 128 rows x 8 x 16B
            const int idx = i * 512 + tid;
            const int r = idx >> 3, c = idx & 7;
            const uint32_t so = swz((uint32_t)(r * 128 + c * 16));
            cp16(st + H2_BH + so, Bh_g + (size_t)(bn + r) * K + k0 + c * 8);
            cp16(st + H2_BL + so, Bl_g + (size_t)(bn + r) * K + k0 + c * 8);
        }
        cp_commit();
    };

    load_chunk(0, 0);
    if (NIT > 1) load_chunk(1, 64);

    const uint32_t lrow = lane & 15;
    const uint32_t lkb  = (lane >> 4) * 16;

    for (int it = 0; it < NIT; it++) {
        const int cur = it & 1;
        if (it + 1 < NIT) cp_wait<1>(); else cp_wait<0>();
        __syncthreads();

        const uint32_t st = tile0 + (uint32_t)cur * H2_STAGE;

        #pragma unroll
        for (int ks = 0; ks < 4; ks++) {
            const uint32_t kb = (uint32_t)ks * 32 + lkb;

            uint32_t ah[4][4];
            #pragma unroll
            for (int mt = 0; mt < 4; mt++)
                ldsm4(ah[mt], st + H2_A + swz((uint32_t)((wm*64 + mt*16 + lrow) * 128) + kb));

            uint32_t bh[2][4], bl[2][4];
            #pragma unroll
            for (int g = 0; g < 2; g++) {
                const uint32_t so = swz((uint32_t)((wn*32 + g*16 + lrow) * 128) + kb);
                ldsm4(bh[g], st + H2_BH + so);
                ldsm4(bl[g], st + H2_BL + so);
            }

            #pragma unroll
            for (int mt = 0; mt < 4; mt++)
                #pragma unroll
                for (int nt = 0; nt < 4; nt++) {
                    const int g = nt >> 1, s2 = nt & 1;
                    uint32_t bf2r[2] = { bh[g][s2], bh[g][s2 + 2] };
                    mma16816h(acc[mt][nt], ah[mt], bf2r);
                }
            #pragma unroll
            for (int mt = 0; mt < 4; mt++)
                #pragma unroll
                for (int nt = 0; nt < 4; nt++) {
                    const int g = nt >> 1, s2 = nt & 1;
                    uint32_t bf2r[2] = { bl[g][s2], bl[g][s2 + 2] };
                    mma16816h(acc[mt][nt], ah[mt], bf2r);
                }
        }
        __syncthreads();
        if (it + 2 < NIT) load_chunk(cur, (it + 2) * 64);
    }

    // ---- epilogue ----
    #pragma unroll
    for (int mt = 0; mt < 4; mt++) {
        const int m0 = bm + wm * 64 + mt * 16 + (lane >> 2);
        #pragma unroll
        for (int nt = 0; nt < 4; nt++) {
            const int n0 = bn + wn * 32 + nt * 8 + (lane & 3) * 2;
            #pragma unroll
            for (int i = 0; i < 4; i++) {
                const int m = m0 + ((i >= 2) ? 8 : 0);
                const int n = n0 + (i & 1);
                float v = acc[mt][nt][i] * scale;

                if (MODE == EP_PLAIN) {
                    ((float*)O0)[(size_t)bz * ((size_t)M * N) + (size_t)m * N + n] = v;
                } else if (MODE == EP_Q16) {
                    v += bias[n];
                    const int b = m >> 11, nn = m & (SEQ - 1);
                    const int h = n >> 7,  d = n & (HD - 1);
                    ((fp16*)O0)[(((size_t)(b*HEADS + h))*SEQ + nn)*HD + d] = __float2half(v);
                } else if (MODE == EP_K) {
                    v += bias[n];
                    const int b = m >> 11, nn = m & (SEQ - 1);
                    const int h = n >> 7,  d = n & (HD - 1);
                    split_write_h((fp16*)O0, (fp16*)O1,
                                  (((size_t)(b*HEADS + h))*SEQ + nn)*HD + d, v);
                } else if (MODE == EP_VT) {
                    v += bias[n];
                    const int b = m >> 11, nn = m & (SEQ - 1);
                    const int h = n >> 7,  d = n & (HD - 1);
                    split_write_h((fp16*)O0, (fp16*)O1,
                                  (((size_t)(b*HEADS + h))*HD + d)*SEQ + nn, v);
                } else if (MODE == EP_MERGE16) {
                    const int b = bz >> 4, h = bz & 15;
                    ((fp16*)O0)[((size_t)(b*SEQ + m))*EMBED + h*HD + n] = __float2half(v);
                } else if (MODE == EP_RES) {
                    v += bias[n] + res[(size_t)m * N + n];
                    ((float*)O0)[(size_t)m * N + n] = v;
                } else { // EP_GELU
                    v += bias[n];
                    v = 0.5f * v * (1.f + erff(v * 0.70710678118654752f));
                    ((fp16*)O0)[(size_t)m * N + n] = __float2half(v);
                }
            }
        }
    }
}

// ---------------- softmax: fp32 in -> fp16 out ----------------
__global__ __launch_bounds__(256)
void softmax_kernel(const float* __restrict__ S, fp16* __restrict__ P)
{
    __shared__ float red[256];
    const size_t row = blockIdx.x;
    const float* p = S + row * (size_t)SEQ;
    const int tid = threadIdx.x;

    float v[8];
    float lmax = -1e30f;
    #pragma unroll
    for (int i = 0; i < 8; i++) { v[i] = p[tid + i*256]; lmax = fmaxf(lmax, v[i]); }
    red[tid] = lmax; __syncthreads();
    for (int s = 128; s > 0; s >>= 1) { if (tid < s) red[tid] = fmaxf(red[tid], red[tid+s]); __syncthreads(); }
    const float m = red[0]; __syncthreads();

    float lsum = 0.f;
    #pragma unroll
    for (int i = 0; i < 8; i++) { v[i] = expf(v[i] - m); lsum += v[i]; }
    red[tid] = lsum; __syncthreads();
    for (int s = 128; s > 0; s >>= 1) { if (tid < s) red[tid] += red[tid+s]; __syncthreads(); }
    const float inv = 1.f / red[0];

    #pragma unroll
    for (int i = 0; i < 8; i++)
        P[row * (size_t)SEQ + tid + i*256] = __float2half(v[i] * inv);
}

// ---------------- LayerNorm ----------------
template<int H16>
__global__ __launch_bounds__(256)
void ln_kernel(const float* __restrict__ in, const float* __restrict__ g,
               const float* __restrict__ b, float* __restrict__ outf,
               fp16* __restrict__ o16)
{
    __shared__ float r1[256], r2[256];
    const size_t row = blockIdx.x;
    const float* p = in + row * (size_t)EMBED;
    const int tid = threadIdx.x;

    float v[8];
    float s = 0.f, ss = 0.f;
    #pragma unroll
    for (int i = 0; i < 8; i++) { v[i] = p[tid + i*256]; s += v[i]; ss += v[i]*v[i]; }
    r1[tid] = s; r2[tid] = ss; __syncthreads();
    for (int st = 128; st > 0; st >>= 1) {
        if (tid < st) { r1[tid] += r1[tid+st]; r2[tid] += r2[tid+st]; }
        __syncthreads();
    }
    const float mu  = r1[0] * (1.f / EMBED);
    const float var = r2[0] * (1.f / EMBED) - mu * mu;
    const float rs  = rsqrtf(var + LN_EPS);

    #pragma unroll
    for (int i = 0; i < 8; i++) {
        const int c = tid + i*256;
        const float o = (v[i] - mu) * rs * g[c] + b[c];
        outf[row * (size_t)EMBED + c] = o;
        if (H16) o16[row * (size_t)EMBED + c] = __float2half(o);
    }
}

// ---------------- launch ----------------
extern "C" void kernel_launch(void* const* d_in, const int* in_sizes, int n_in,
                              void* d_out, int out_size)
{
    const float* x   = (const float*)d_in[0];
    const float* Wq  = (const float*)d_in[1];
    const float* bq  = (const float*)d_in[2];
    const float* Wk  = (const float*)d_in[3];
    const float* bk  = (const float*)d_in[4];
    const float* Wv  = (const float*)d_in[5];
    const float* bv  = (const float*)d_in[6];
    const float* Wo  = (const float*)d_in[7];
    const float* bo  = (const float*)d_in[8];
    const float* g1  = (const float*)d_in[9];
    const float* b1  = (const float*)d_in[10];
    const float* g2  = (const float*)d_in[11];
    const float* b2  = (const float*)d_in[12];
    const float* W1  = (const float*)d_in[13];
    const float* bf1 = (const float*)d_in[14];
    const float* W2  = (const float*)d_in[15];
    const float* bf2 = (const float*)d_in[16];
    float* out = (float*)d_out;

    fp16 *x16,*q16,*khi,*klo,*vthi,*vtlo,*p16;
    fp16 *wqh,*wql,*wkh,*wkl,*wvh,*wvl,*woh,*wol,*w1h,*w1l,*w2h,*w2l;
    float *s, *t1, *h;
    cudaGetSymbolAddress((void**)&x16, g_x16);
    cudaGetSymbolAddress((void**)&q16, g_q16);
    cudaGetSymbolAddress((void**)&khi, g_khi); cudaGetSymbolAddress((void**)&klo, g_klo);
    cudaGetSymbolAddress((void**)&vthi,g_vthi);cudaGetSymbolAddress((void**)&vtlo,g_vtlo);
    cudaGetSymbolAddress((void**)&s,   g_s);
    cudaGetSymbolAddress((void**)&p16, g_p16);
    cudaGetSymbolAddress((void**)&t1,  g_t1);  cudaGetSymbolAddress((void**)&h,   g_h);
    cudaGetSymbolAddress((void**)&wqh, g_wqh); cudaGetSymbolAddress((void**)&wql, g_wql);
    cudaGetSymbolAddress((void**)&wkh, g_wkh); cudaGetSymbolAddress((void**)&wkl, g_wkl);
    cudaGetSymbolAddress((void**)&wvh, g_wvh); cudaGetSymbolAddress((void**)&wvl, g_wvl);
    cudaGetSymbolAddress((void**)&woh, g_woh); cudaGetSymbolAddress((void**)&wol, g_wol);
    cudaGetSymbolAddress((void**)&w1h, g_w1h); cudaGetSymbolAddress((void**)&w1l, g_w1l);
    cudaGetSymbolAddress((void**)&w2h, g_w2h); cudaGetSymbolAddress((void**)&w2l, g_w2l);

    // lifetime-disjoint overlays (s dead after softmax; q16 dead after scores)
    fp16* f116 = (fp16*)s;                                   // FFN hidden (67 MB, within s arena)
    fp16* h16  = (fp16*)((char*)s + ((size_t)64 << 20));     // LN1 fp16 copy (17 MB, after f116)
    fp16* ao16 = q16;                                        // attention out [B,N,C]

    cudaFuncSetAttribute(hgemm<EP_PLAIN>,   cudaFuncAttributeMaxDynamicSharedMemorySize, SMEM_DYN_H2);
    cudaFuncSetAttribute(hgemm<EP_Q16>,     cudaFuncAttributeMaxDynamicSharedMemorySize, SMEM_DYN_H2);
    cudaFuncSetAttribute(hgemm<EP_K>,       cudaFuncAttributeMaxDynamicSharedMemorySize, SMEM_DYN_H2);
    cudaFuncSetAttribute(hgemm<EP_VT>,      cudaFuncAttributeMaxDynamicSharedMemorySize, SMEM_DYN_H2);
    cudaFuncSetAttribute(hgemm<EP_MERGE16>, cudaFuncAttributeMaxDynamicSharedMemorySize, SMEM_DYN_H2);
    cudaFuncSetAttribute(hgemm<EP_RES>,     cudaFuncAttributeMaxDynamicSharedMemorySize, SMEM_DYN_H2);
    cudaFuncSetAttribute(hgemm<EP_GELU>,    cudaFuncAttributeMaxDynamicSharedMemorySize, SMEM_DYN_H2);

    const float att_scale = 0.08838834764831845f; // 1/sqrt(128)

    // #1: x -> fp16 ; #2: fused weight prep
    cvt16_kernel<<<(TOKENS*(size_t)EMBED + 1023)/1024, 256>>>(x, x16, (size_t)TOKENS*EMBED);
    prep_weights<<<49152, 256>>>(Wq, Wk, Wv, Wo, W1, W2);

    // #3,#4,#5: QKV projections
    dim3 gQKV(EMBED/128, TOKENS/256, 1);
    hgemm<EP_Q16><<<gQKV, 512, SMEM_DYN_H2>>>(x16, wqh, wql, bq, nullptr, q16, nullptr, TOKENS, EMBED, EMBED, 1.f, 0, 0);
    hgemm<EP_K>  <<<gQKV, 512, SMEM_DYN_H2>>>(x16, wkh, wkl, bk, nullptr, khi, klo,     TOKENS, EMBED, EMBED, 1.f, 0, 0);
    hgemm<EP_VT> <<<gQKV, 512, SMEM_DYN_H2>>>(x16, wvh, wvl, bv, nullptr, vthi, vtlo,   TOKENS, EMBED, EMBED, 1.f, 0, 0);

    // #6: scores = scale * Q @ K^T  <-- ncu -s 5 -c 1 profiles this
    dim3 gS(SEQ/128, SEQ/256, BATCH*HEADS);
    hgemm<EP_PLAIN><<<gS, 512, SMEM_DYN_H2>>>(q16, khi, klo, nullptr, nullptr, s, nullptr,
                                              SEQ, SEQ, HD, att_scale, (long)SEQ*HD, (long)SEQ*HD);
    softmax_kernel<<<BATCH*HEADS*SEQ, 256>>>(s, p16);

    // O = P @ V^T  (ao16 aliases q16, which is dead now)
    dim3 gPV(1, SEQ/256, BATCH*HEADS);
    hgemm<EP_MERGE16><<<gPV, 512, SMEM_DYN_H2>>>(p16, vthi, vtlo, nullptr, nullptr, ao16, nullptr,
                                                 SEQ, HD, SEQ, 1.f, (long)SEQ*SEQ, (long)HD*SEQ);

    // out-proj + residual, LN1 (h16 lives in the dead s arena)
    dim3 gWo(EMBED/128, TOKENS/256, 1);
    hgemm<EP_RES><<<gWo, 512, SMEM_DYN_H2>>>(ao16, woh, wol, bo, x, t1, nullptr,
                                             TOKENS, EMBED, EMBED, 1.f, 0, 0);
    ln_kernel<1><<<TOKENS, 256>>>(t1, g1, b1, h, h16);

    // FFN (f116 lives in the dead s arena)
    dim3 gF1(DFF/128, TOKENS/256, 1);
    hgemm<EP_GELU><<<gF1, 512, SMEM_DYN_H2>>>(h16, w1h, w1l, bf1, nullptr, f116, nullptr,
                                              TOKENS, DFF, EMBED, 1.f, 0, 0);
    dim3 gF2(EMBED/128, TOKENS/256, 1);
    hgemm<EP_RES><<<gF2, 512, SMEM_DYN_H2>>>(f116, w2h, w2l, bf2, h, t1, nullptr,
                                             TOKENS, EMBED, DFF, 1.f, 0, 0);

    ln_kernel<0><<<TOKENS, 256>>>(t1, g2, b2, out, nullptr);
}

// round 16
// speedup vs baseline: 2.3228x; 1.6025x over previous
#include <cuda_runtime.h>
#include <cuda_fp16.h>
#include <math.h>
#include <stdint.h>

#define EMBED 2048
#define HEADS 16
#define HD    128
#define DFF   8192
#define BATCH 2
#define SEQ   2048
#define TOKENS (BATCH*SEQ)
#define LN_EPS 1e-5f

typedef __half fp16;

// ---------------- scratch ----------------
// f116/h16 alias into g_s (dead after softmax); ao16 aliases g_q16 (dead after scores).
__device__ __align__(1024) fp16 g_x16[(size_t)TOKENS*EMBED];
__device__ __align__(1024) fp16 g_q16[(size_t)TOKENS*EMBED];                         // also ao16
__device__ __align__(1024) fp16 g_k16[(size_t)TOKENS*EMBED];                         // [B,H,N,hd]
__device__ __align__(1024) fp16 g_vt16[(size_t)TOKENS*EMBED];                        // [B,H,hd,N]
__device__ __align__(1024) float g_s [(size_t)BATCH*HEADS*SEQ*SEQ];                  // also f116,h16
__device__ __align__(1024) fp16 g_p16[(size_t)BATCH*HEADS*SEQ*SEQ];
__device__ __align__(1024) float g_t1[(size_t)TOKENS*EMBED];
__device__ __align__(1024) float g_h [(size_t)TOKENS*EMBED];
__device__ __align__(1024) fp16 g_wq16[(size_t)EMBED*EMBED];
__device__ __align__(1024) fp16 g_wk16[(size_t)EMBED*EMBED];
__device__ __align__(1024) fp16 g_wv16[(size_t)EMBED*EMBED];
__device__ __align__(1024) fp16 g_wo16[(size_t)EMBED*EMBED];
__device__ __align__(1024) fp16 g_w116[(size_t)EMBED*DFF];
__device__ __align__(1024) fp16 g_w216[(size_t)EMBED*DFF];

// ---------------- helpers ----------------
__device__ __forceinline__ uint32_t smem_u32(const void* p) {
    return (uint32_t)__cvta_generic_to_shared(p);
}
__device__ __forceinline__ void cp16(uint32_t dst, const void* src) {
    asm volatile("cp.async.cg.shared.global [%0], [%1], 16;\n" :: "r"(dst), "l"(src));
}
__device__ __forceinline__ void cp_commit() { asm volatile("cp.async.commit_group;\n"); }
template<int Ngrp> __device__ __forceinline__ void cp_wait() {
    asm volatile("cp.async.wait_group %0;\n" :: "n"(Ngrp));
}
__device__ __forceinline__ void ldsm4(uint32_t* r, uint32_t addr) {
    asm volatile("ldmatrix.sync.aligned.m8n8.x4.shared.b16 {%0,%1,%2,%3}, [%4];"
                 : "=r"(r[0]), "=r"(r[1]), "=r"(r[2]), "=r"(r[3]) : "r"(addr));
}
__device__ __forceinline__ void mma16816h(float* c, const uint32_t* a, const uint32_t* b) {
    asm volatile(
        "mma.sync.aligned.m16n8k16.row.col.f32.f16.f16.f32 "
        "{%0,%1,%2,%3}, {%4,%5,%6,%7}, {%8,%9}, {%0,%1,%2,%3};\n"
        : "+f"(c[0]), "+f"(c[1]), "+f"(c[2]), "+f"(c[3])
        : "r"(a[0]), "r"(a[1]), "r"(a[2]), "r"(a[3]), "r"(b[0]), "r"(b[1]));
}
__device__ __forceinline__ uint32_t swz(uint32_t off) { return off ^ ((off >> 3) & 0x70); }

// ---------------- fused weight prep: transpose -> single fp16 ----------------
__global__ __launch_bounds__(256)
void prep_weights(const float* __restrict__ Wq, const float* __restrict__ Wk,
                  const float* __restrict__ Wv, const float* __restrict__ Wo,
                  const float* __restrict__ W1, const float* __restrict__ W2)
{
    __shared__ float t[32][33];
    const int bidx = blockIdx.x;

    const float* in; fp16* o; int R, C, tbase;
    if (bidx < 16384) {
        R = EMBED; C = EMBED;
        if (bidx < 4096)       { in = Wq; o = g_wq16; tbase = 0; }
        else if (bidx < 8192)  { in = Wk; o = g_wk16; tbase = 4096; }
        else if (bidx < 12288) { in = Wv; o = g_wv16; tbase = 8192; }
        else                   { in = Wo; o = g_wo16; tbase = 12288; }
    } else if (bidx < 32768) {
        in = W1; o = g_w116; R = EMBED; C = DFF; tbase = 16384;
    } else {
        in = W2; o = g_w216; R = DFF; C = EMBED; tbase = 32768;
    }
    const int t0 = bidx - tbase;
    const int tiles_x = C >> 5;
    const int c0 = (t0 % tiles_x) << 5;
    const int r0 = (t0 / tiles_x) << 5;

    const int tx = threadIdx.x & 31, ty = threadIdx.x >> 5;
    #pragma unroll
    for (int i = 0; i < 32; i += 8)
        t[ty + i][tx] = in[(size_t)(r0 + ty + i) * C + c0 + tx];
    __syncthreads();
    #pragma unroll
    for (int i = 0; i < 32; i += 8)
        o[(size_t)(c0 + ty + i) * R + r0 + tx] = __float2half(t[tx][ty + i]);
}

// ---------------- elementwise fp32 -> fp16 ----------------
__global__ __launch_bounds__(256)
void cvt16_kernel(const float* __restrict__ in, fp16* __restrict__ o, size_t n)
{
    size_t i = (size_t)blockIdx.x * 1024 + threadIdx.x;
    #pragma unroll
    for (int j = 0; j < 4; j++) {
        size_t off = i + (size_t)j * 256;
        if (off < n) o[off] = __float2half(in[off]);
    }
}

// ---------------- single-fp16 mma.sync GEMM ----------------
// D = scale * A(fp16) @ B(fp16)^T (+bias/epilogue); 1 MMA per fragment.
// CTA tile 256x128, 16 warps (512 thr) of 64x32, K-chunk 64, double buffered.
enum { EP_PLAIN=0, EP_QK16=1, EP_VT=2, EP_MERGE16=3, EP_RES=4, EP_GELU=5 };

#define H1_A  0
#define H1_B  32768
#define H1_STAGE 49152
#define SMEM_DYN_H1 (2*H1_STAGE + 1024)

template<int MODE>
__global__ __launch_bounds__(512)
void hgemm(const fp16* __restrict__ A, const fp16* __restrict__ B,
           const float* __restrict__ bias, const float* __restrict__ res,
           void* __restrict__ O0,
           int M, int N, int K, float scale, long sA, long sB)
{
    extern __shared__ char dsm[];
    const uint32_t tile0 = (smem_u32(dsm) + 1023u) & ~1023u;

    const int tid = threadIdx.x, warp = tid >> 5, lane = tid & 31;
    const int wm = warp >> 2;       // 0..3 -> m offset 64
    const int wn = warp & 3;        // 0..3 -> n offset 32
    const int bz = blockIdx.z;
    const int bm = blockIdx.y * 256, bn = blockIdx.x * 128;

    const fp16* A_g = A + (size_t)bz * sA;
    const fp16* B_g = B + (size_t)bz * sB;

    float acc[4][4][4];
    #pragma unroll
    for (int i = 0; i < 4; i++)
        #pragma unroll
        for (int j = 0; j < 4; j++)
            #pragma unroll
            for (int p = 0; p < 4; p++) acc[i][j][p] = 0.f;

    const int NIT = K >> 6;

    auto load_chunk = [&](int stage, int k0) {
        const uint32_t st = tile0 + (uint32_t)stage * H1_STAGE;
        #pragma unroll
        for (int i = 0; i < 4; i++) {              // A: 256 rows x 8 x 16B
            const int idx = i * 512 + tid;
            const int r = idx >> 3, c = idx & 7;
            const uint32_t so = swz((uint32_t)(r * 128 + c * 16));
            cp16(st + H1_A + so, A_g + (size_t)(bm + r) * K + k0 + c * 8);
        }
        #pragma unroll
        for (int i = 0; i < 2; i++) {              // B: 128 rows x 8 x 16B
            const int idx = i * 512 + tid;
            const int r = idx >> 3, c = idx & 7;
            const uint32_t so = swz((uint32_t)(r * 128 + c * 16));
            cp16(st + H1_B + so, B_g + (size_t)(bn + r) * K + k0 + c * 8);
        }
        cp_commit();
    };

    load_chunk(0, 0);
    if (NIT > 1) load_chunk(1, 64);

    const uint32_t lrow = lane & 15;
    const uint32_t lkb  = (lane >> 4) * 16;

    for (int it = 0; it < NIT; it++) {
        const int cur = it & 1;
        if (it + 1 < NIT) cp_wait<1>(); else cp_wait<0>();
        __syncthreads();

        const uint32_t st = tile0 + (uint32_t)cur * H1_STAGE;

        #pragma unroll
        for (int ks = 0; ks < 4; ks++) {
            const uint32_t kb = (uint32_t)ks * 32 + lkb;

            uint32_t ah[4][4];
            #pragma unroll
            for (int mt = 0; mt < 4; mt++)
                ldsm4(ah[mt], st + H1_A + swz((uint32_t)((wm*64 + mt*16 + lrow) * 128) + kb));

            uint32_t bh[2][4];
            #pragma unroll
            for (int g = 0; g < 2; g++)
                ldsm4(bh[g], st + H1_B + swz((uint32_t)((wn*32 + g*16 + lrow) * 128) + kb));

            #pragma unroll
            for (int mt = 0; mt < 4; mt++)
                #pragma unroll
                for (int nt = 0; nt < 4; nt++) {
                    const int g = nt >> 1, s2 = nt & 1;
                    uint32_t bf2r[2] = { bh[g][s2], bh[g][s2 + 2] };
                    mma16816h(acc[mt][nt], ah[mt], bf2r);
                }
        }
        __syncthreads();
        if (it + 2 < NIT) load_chunk(cur, (it + 2) * 64);
    }

    // ---- epilogue ----
    #pragma unroll
    for (int mt = 0; mt < 4; mt++) {
        const int m0 = bm + wm * 64 + mt * 16 + (lane >> 2);
        #pragma unroll
        for (int nt = 0; nt < 4; nt++) {
            const int n0 = bn + wn * 32 + nt * 8 + (lane & 3) * 2;
            #pragma unroll
            for (int i = 0; i < 4; i++) {
                const int m = m0 + ((i >= 2) ? 8 : 0);
                const int n = n0 + (i & 1);
                float v = acc[mt][nt][i] * scale;

                if (MODE == EP_PLAIN) {
                    ((float*)O0)[(size_t)bz * ((size_t)M * N) + (size_t)m * N + n] = v;
                } else if (MODE == EP_QK16) {
                    v += bias[n];
                    const int b = m >> 11, nn = m & (SEQ - 1);
                    const int h = n >> 7,  d = n & (HD - 1);
                    ((fp16*)O0)[(((size_t)(b*HEADS + h))*SEQ + nn)*HD + d] = __float2half(v);
                } else if (MODE == EP_VT) {
                    v += bias[n];
                    const int b = m >> 11, nn = m & (SEQ - 1);
                    const int h = n >> 7,  d = n & (HD - 1);
                    ((fp16*)O0)[(((size_t)(b*HEADS + h))*HD + d)*SEQ + nn] = __float2half(v);
                } else if (MODE == EP_MERGE16) {
                    const int b = bz >> 4, h = bz & 15;
                    ((fp16*)O0)[((size_t)(b*SEQ + m))*EMBED + h*HD + n] = __float2half(v);
                } else if (MODE == EP_RES) {
                    v += bias[n] + res[(size_t)m * N + n];
                    ((float*)O0)[(size_t)m * N + n] = v;
                } else { // EP_GELU
                    v += bias[n];
                    v = 0.5f * v * (1.f + erff(v * 0.70710678118654752f));
                    ((fp16*)O0)[(size_t)m * N + n] = __float2half(v);
                }
            }
        }
    }
}

// ---------------- softmax: fp32 in -> fp16 out ----------------
__global__ __launch_bounds__(256)
void softmax_kernel(const float* __restrict__ S, fp16* __restrict__ P)
{
    __shared__ float red[256];
    const size_t row = blockIdx.x;
    const float* p = S + row * (size_t)SEQ;
    const int tid = threadIdx.x;

    float v[8];
    float lmax = -1e30f;
    #pragma unroll
    for (int i = 0; i < 8; i++) { v[i] = p[tid + i*256]; lmax = fmaxf(lmax, v[i]); }
    red[tid] = lmax; __syncthreads();
    for (int s = 128; s > 0; s >>= 1) { if (tid < s) red[tid] = fmaxf(red[tid], red[tid+s]); __syncthreads(); }
    const float m = red[0]; __syncthreads();

    float lsum = 0.f;
    #pragma unroll
    for (int i = 0; i < 8; i++) { v[i] = expf(v[i] - m); lsum += v[i]; }
    red[tid] = lsum; __syncthreads();
    for (int s = 128; s > 0; s >>= 1) { if (tid < s) red[tid] += red[tid+s]; __syncthreads(); }
    const float inv = 1.f / red[0];

    #pragma unroll
    for (int i = 0; i < 8; i++)
        P[row * (size_t)SEQ + tid + i*256] = __float2half(v[i] * inv);
}

// ---------------- LayerNorm ----------------
template<int H16>
__global__ __launch_bounds__(256)
void ln_kernel(const float* __restrict__ in, const float* __restrict__ g,
               const float* __restrict__ b, float* __restrict__ outf,
               fp16* __restrict__ o16)
{
    __shared__ float r1[256], r2[256];
    const size_t row = blockIdx.x;
    const float* p = in + row * (size_t)EMBED;
    const int tid = threadIdx.x;

    float v[8];
    float s = 0.f, ss = 0.f;
    #pragma unroll
    for (int i = 0; i < 8; i++) { v[i] = p[tid + i*256]; s += v[i]; ss += v[i]*v[i]; }
    r1[tid] = s; r2[tid] = ss; __syncthreads();
    for (int st = 128; st > 0; st >>= 1) {
        if (tid < st) { r1[tid] += r1[tid+st]; r2[tid] += r2[tid+st]; }
        __syncthreads();
    }
    const float mu  = r1[0] * (1.f / EMBED);
    const float var = r2[0] * (1.f / EMBED) - mu * mu;
    const float rs  = rsqrtf(var + LN_EPS);

    #pragma unroll
    for (int i = 0; i < 8; i++) {
        const int c = tid + i*256;
        const float o = (v[i] - mu) * rs * g[c] + b[c];
        outf[row * (size_t)EMBED + c] = o;
        if (H16) o16[row * (size_t)EMBED + c] = __float2half(o);
    }
}

// ---------------- launch ----------------
extern "C" void kernel_launch(void* const* d_in, const int* in_sizes, int n_in,
                              void* d_out, int out_size)
{
    const float* x   = (const float*)d_in[0];
    const float* Wq  = (const float*)d_in[1];
    const float* bq  = (const float*)d_in[2];
    const float* Wk  = (const float*)d_in[3];
    const float* bk  = (const float*)d_in[4];
    const float* Wv  = (const float*)d_in[5];
    const float* bv  = (const float*)d_in[6];
    const float* Wo  = (const float*)d_in[7];
    const float* bo  = (const float*)d_in[8];
    const float* g1  = (const float*)d_in[9];
    const float* b1  = (const float*)d_in[10];
    const float* g2  = (const float*)d_in[11];
    const float* b2  = (const float*)d_in[12];
    const float* W1  = (const float*)d_in[13];
    const float* bf1 = (const float*)d_in[14];
    const float* W2  = (const float*)d_in[15];
    const float* bf2 = (const float*)d_in[16];
    float* out = (float*)d_out;

    fp16 *x16,*q16,*k16,*vt16,*p16;
    fp16 *wq16,*wk16,*wv16,*wo16,*w116,*w216;
    float *s, *t1, *h;
    cudaGetSymbolAddress((void**)&x16, g_x16);
    cudaGetSymbolAddress((void**)&q16, g_q16);
    cudaGetSymbolAddress((void**)&k16, g_k16);
    cudaGetSymbolAddress((void**)&vt16,g_vt16);
    cudaGetSymbolAddress((void**)&s,   g_s);
    cudaGetSymbolAddress((void**)&p16, g_p16);
    cudaGetSymbolAddress((void**)&t1,  g_t1);  cudaGetSymbolAddress((void**)&h, g_h);
    cudaGetSymbolAddress((void**)&wq16,g_wq16);
    cudaGetSymbolAddress((void**)&wk16,g_wk16);
    cudaGetSymbolAddress((void**)&wv16,g_wv16);
    cudaGetSymbolAddress((void**)&wo16,g_wo16);
    cudaGetSymbolAddress((void**)&w116,g_w116);
    cudaGetSymbolAddress((void**)&w216,g_w216);

    // lifetime-disjoint overlays (s dead after softmax; q16 dead after scores)
    fp16* f116 = (fp16*)s;                                   // FFN hidden (67 MB)
    fp16* h16  = (fp16*)((char*)s + ((size_t)64 << 20));     // LN1 fp16 copy
    fp16* ao16 = q16;                                        // attention out [B,N,C]

    cudaFuncSetAttribute(hgemm<EP_PLAIN>,   cudaFuncAttributeMaxDynamicSharedMemorySize, SMEM_DYN_H1);
    cudaFuncSetAttribute(hgemm<EP_QK16>,    cudaFuncAttributeMaxDynamicSharedMemorySize, SMEM_DYN_H1);
    cudaFuncSetAttribute(hgemm<EP_VT>,      cudaFuncAttributeMaxDynamicSharedMemorySize, SMEM_DYN_H1);
    cudaFuncSetAttribute(hgemm<EP_MERGE16>, cudaFuncAttributeMaxDynamicSharedMemorySize, SMEM_DYN_H1);
    cudaFuncSetAttribute(hgemm<EP_RES>,     cudaFuncAttributeMaxDynamicSharedMemorySize, SMEM_DYN_H1);
    cudaFuncSetAttribute(hgemm<EP_GELU>,    cudaFuncAttributeMaxDynamicSharedMemorySize, SMEM_DYN_H1);

    const float att_scale = 0.08838834764831845f; // 1/sqrt(128)

    // #1: x -> fp16 ; #2: fused weight prep
    cvt16_kernel<<<(TOKENS*(size_t)EMBED + 1023)/1024, 256>>>(x, x16, (size_t)TOKENS*EMBED);
    prep_weights<<<49152, 256>>>(Wq, Wk, Wv, Wo, W1, W2);

    // #3,#4,#5: QKV projections
    dim3 gQKV(EMBED/128, TOKENS/256, 1);
    hgemm<EP_QK16><<<gQKV, 512, SMEM_DYN_H1>>>(x16, wq16, bq, nullptr, q16,  TOKENS, EMBED, EMBED, 1.f, 0, 0);
    hgemm<EP_QK16><<<gQKV, 512, SMEM_DYN_H1>>>(x16, wk16, bk, nullptr, k16,  TOKENS, EMBED, EMBED, 1.f, 0, 0);
    hgemm<EP_VT>  <<<gQKV, 512, SMEM_DYN_H1>>>(x16, wv16, bv, nullptr, vt16, TOKENS, EMBED, EMBED, 1.f, 0, 0);

    // #6: scores = scale * Q @ K^T  <-- ncu -s 5 -c 1 profiles this
    dim3 gS(SEQ/128, SEQ/256, BATCH*HEADS);
    hgemm<EP_PLAIN><<<gS, 512, SMEM_DYN_H1>>>(q16, k16, nullptr, nullptr, s,
                                              SEQ, SEQ, HD, att_scale, (long)SEQ*HD, (long)SEQ*HD);
    softmax_kernel<<<BATCH*HEADS*SEQ, 256>>>(s, p16);

    // O = P @ V^T  (ao16 aliases q16)
    dim3 gPV(1, SEQ/256, BATCH*HEADS);
    hgemm<EP_MERGE16><<<gPV, 512, SMEM_DYN_H1>>>(p16, vt16, nullptr, nullptr, ao16,
                                                 SEQ, HD, SEQ, 1.f, (long)SEQ*SEQ, (long)HD*SEQ);

    // out-proj + residual, LN1
    dim3 gWo(EMBED/128, TOKENS/256, 1);
    hgemm<EP_RES><<<gWo, 512, SMEM_DYN_H1>>>(ao16, wo16, bo, x, t1,
                                             TOKENS, EMBED, EMBED, 1.f, 0, 0);
    ln_kernel<1><<<TOKENS, 256>>>(t1, g1, b1, h, h16);

    // FFN
    dim3 gF1(DFF/128, TOKENS/256, 1);
    hgemm<EP_GELU><<<gF1, 512, SMEM_DYN_H1>>>(h16, w116, bf1, nullptr, f116,
                                              TOKENS, DFF, EMBED, 1.f, 0, 0);
    dim3 gF2(EMBED/128, TOKENS/256, 1);
    hgemm<EP_RES><<<gF2, 512, SMEM_DYN_H1>>>(f116, w216, bf2, h, t1,
                                             TOKENS, EMBED, DFF, 1.f, 0, 0);

    ln_kernel<0><<<TOKENS, 256>>>(t1, g2, b2, out, nullptr);
}